// round 12
// baseline (speedup 1.0000x reference)
#include <cuda_runtime.h>
#include <cuda_bf16.h>
#include <math.h>
#include <stdint.h>

#define Nn   6000
#define Ee   192000
#define CINc 32
#define CHID 64
#define Kk   125
#define KX   4000        // Kk*CINc
#define KH   8000        // Kk*CHID

// ---------------- device scratch ----------------
__device__ __nv_bfloat16 g_Tx[(size_t)Nn * KX];   // bf16, pre-scaled by 1/deg
__device__ __nv_bfloat16 g_Th[(size_t)Nn * KH];
__device__ __nv_bfloat16 g_Btx[192 * KX];         // [co,k]: {Wxr,Wxz,Wxn} transposed
__device__ __nv_bfloat16 g_Bth[128 * KH];         // [co,k]: {Whr,Whz} transposed
__device__ float g_part[7][Nn * CHID];            // 0=XR 1=XZ 2=XN 3,4=HR halves 5,6=HZ halves
__device__ int   g_deg[Nn];
__device__ int   g_fill[Nn];
__device__ int   g_rowstart[Nn + 1];
__device__ int   g_csr[Ee];
__device__ int   g_bidx[Ee * 8];
__device__ float g_bval[Ee * 8];

// ---------------- PTX helpers (compute_103-safe: sm_80+ features only) ----------------
__device__ __forceinline__ uint32_t smem_u32(const void* p) {
    uint32_t a;
    asm("{ .reg .u64 t; cvta.to.shared.u64 t, %1; cvt.u32.u64 %0, t; }" : "=r"(a) : "l"(p));
    return a;
}
__device__ __forceinline__ void cpasync16(uint32_t dst, const void* src, int src_bytes) {
    asm volatile("cp.async.cg.shared.global [%0], [%1], 16, %2;"
                 :: "r"(dst), "l"(src), "r"(src_bytes) : "memory");
}
#define CP_COMMIT() asm volatile("cp.async.commit_group;" ::: "memory")
#define WAITG(n)    asm volatile("cp.async.wait_group " #n ";" ::: "memory")

__device__ __forceinline__ uint32_t lds32(uint32_t a) {
    uint32_t v;
    asm volatile("ld.shared.b32 %0, [%1];" : "=r"(v) : "r"(a));
    return v;
}
__device__ __forceinline__ void mma16(float* d, const uint32_t* a, uint32_t b0, uint32_t b1) {
    asm volatile(
        "mma.sync.aligned.m16n8k16.row.col.f32.bf16.bf16.f32 "
        "{%0,%1,%2,%3}, {%4,%5,%6,%7}, {%8,%9}, {%0,%1,%2,%3};"
        : "+f"(d[0]), "+f"(d[1]), "+f"(d[2]), "+f"(d[3])
        : "r"(a[0]), "r"(a[1]), "r"(a[2]), "r"(a[3]), "r"(b0), "r"(b1));
}

// ---------------- kernel 0: zero per-call counters ----------------
__global__ void k_zero() {
    int i = blockIdx.x * blockDim.x + threadIdx.x;
    if (i < Nn) { g_deg[i] = 0; g_fill[i] = 0; }
}

// ---------------- kernel 1: per-edge basis/index + degree histogram ----------------
__global__ void k_edge(const float* __restrict__ attr, const int* __restrict__ ei) {
    int e = blockIdx.x * blockDim.x + threadIdx.x;
    if (e >= Ee) return;
    float fr[3]; int i0[3];
#pragma unroll
    for (int d = 0; d < 3; d++) {
        float u = attr[e * 3 + d] * 4.0f;
        int i = (int)floorf(u);
        i = i < 0 ? 0 : (i > 3 ? 3 : i);
        fr[d] = u - (float)i;
        i0[d] = i;
    }
#pragma unroll
    for (int s = 0; s < 8; s++) {
        int b0 = s & 1, b1 = (s >> 1) & 1, b2 = (s >> 2) & 1;
        int idx = (i0[0] + b0) * 25 + (i0[1] + b1) * 5 + (i0[2] + b2);
        float w = (b0 ? fr[0] : 1.0f - fr[0]) *
                  (b1 ? fr[1] : 1.0f - fr[1]) *
                  (b2 ? fr[2] : 1.0f - fr[2]);
        g_bidx[e * 8 + s] = idx;
        g_bval[e * 8 + s] = w;
    }
    atomicAdd(&g_deg[ei[Ee + e]], 1);
}

// ---------------- kernel 2: exclusive scan (single block) ----------------
__global__ void k_scan() {
    __shared__ int sh[1024];
    int tid = threadIdx.x;
    const int CH = 6;
    int base = tid * CH;
    int local[CH];
    int sum = 0;
#pragma unroll
    for (int q = 0; q < CH; q++) {
        int i = base + q;
        int v = (i < Nn) ? g_deg[i] : 0;
        local[q] = sum;
        sum += v;
    }
    sh[tid] = sum;
    __syncthreads();
    for (int off = 1; off < 1024; off <<= 1) {
        int v = 0;
        if (tid >= off) v = sh[tid - off];
        __syncthreads();
        sh[tid] += v;
        __syncthreads();
    }
    int excl = (tid > 0) ? sh[tid - 1] : 0;
#pragma unroll
    for (int q = 0; q < CH; q++) {
        int i = base + q;
        if (i < Nn) g_rowstart[i] = excl + local[q];
    }
    if (tid == 1023) g_rowstart[Nn] = sh[1023];
}

// ---------------- kernel 3: CSR fill ----------------
__global__ void k_fill(const int* __restrict__ ei) {
    int e = blockIdx.x * blockDim.x + threadIdx.x;
    if (e >= Ee) return;
    int dst = ei[Ee + e];
    int p = atomicAdd(&g_fill[dst], 1);
    g_csr[g_rowstart[dst] + p] = e;
}

// ---------------- kernel 4: per-node scatter (software-pipelined, depth 2) ----------------
__global__ __launch_bounds__(96) void k_scatter(const float* __restrict__ x,
                                                const float* __restrict__ hidden,
                                                const int* __restrict__ ei) {
    __shared__ float Tsh[Kk * 96];
    int n = blockIdx.x;
    int c = threadIdx.x;
#pragma unroll 5
    for (int k = 0; k < Kk; k++) Tsh[k * 96 + c] = 0.0f;
    int rs = g_rowstart[n], re = g_rowstart[n + 1];
    float inv = 1.0f / (float)max(re - rs, 1);
    __syncthreads();

    // stage regs: deps for edge j (cur) and edge id for j+1
    int   e_nx = 0;
    int4  ia_c, ib_c;
    float4 va_c, vb_c;
    float xv_c = 0.0f;

    if (rs < re) {
        int e0 = __ldg(&g_csr[rs]);
        if (rs + 1 < re) e_nx = __ldg(&g_csr[rs + 1]);
        int src = __ldg(&ei[e0]);
        xv_c = (c < CINc) ? __ldg(&x[src * CINc + c])
                          : __ldg(&hidden[src * CHID + (c - CINc)]);
        const int4*   bip = (const int4*)(g_bidx + (size_t)e0 * 8);
        const float4* bvp = (const float4*)(g_bval + (size_t)e0 * 8);
        ia_c = __ldg(bip); ib_c = __ldg(bip + 1);
        va_c = __ldg(bvp); vb_c = __ldg(bvp + 1);
    }

#pragma unroll 1
    for (int j = rs; j < re; j++) {
        // snapshot current edge's operands
        int4  ia = ia_c, ib = ib_c;
        float4 va = va_c, vb = vb_c;
        float xv = xv_c;

        // issue next-next csr and next-edge dependent loads BEFORE the smem RMWs
        int e_cur_nx = e_nx;
        if (j + 2 < re) e_nx = __ldg(&g_csr[j + 2]);
        if (j + 1 < re) {
            int src = __ldg(&ei[e_cur_nx]);
            xv_c = (c < CINc) ? __ldg(&x[src * CINc + c])
                              : __ldg(&hidden[src * CHID + (c - CINc)]);
            const int4*   bip = (const int4*)(g_bidx + (size_t)e_cur_nx * 8);
            const float4* bvp = (const float4*)(g_bval + (size_t)e_cur_nx * 8);
            ia_c = __ldg(bip); ib_c = __ldg(bip + 1);
            va_c = __ldg(bvp); vb_c = __ldg(bvp + 1);
        }

        // 8 corner indices within an edge are distinct; thread owns column c
        Tsh[ia.x * 96 + c] += va.x * xv;
        Tsh[ia.y * 96 + c] += va.y * xv;
        Tsh[ia.z * 96 + c] += va.z * xv;
        Tsh[ia.w * 96 + c] += va.w * xv;
        Tsh[ib.x * 96 + c] += vb.x * xv;
        Tsh[ib.y * 96 + c] += vb.y * xv;
        Tsh[ib.z * 96 + c] += vb.z * xv;
        Tsh[ib.w * 96 + c] += vb.w * xv;
    }
    __syncthreads();

    if (c < CINc) {
        __nv_bfloat16* o = g_Tx + (size_t)n * KX + c;
#pragma unroll 5
        for (int k = 0; k < Kk; k++) o[k * CINc] = __float2bfloat16(Tsh[k * 96 + c] * inv);
    } else {
        __nv_bfloat16* o = g_Th + (size_t)n * KH + (c - CINc);
#pragma unroll 5
        for (int k = 0; k < Kk; k++) o[k * CHID] = __float2bfloat16(Tsh[k * 96 + c] * inv);
    }
}

// ---------------- kernel 5: transpose W -> Bt [N,K] K-major, bf16 ----------------
__global__ void k_transpose(const float* __restrict__ Wxr, const float* __restrict__ Wxz,
                            const float* __restrict__ Wxn, const float* __restrict__ Whr,
                            const float* __restrict__ Whz) {
    __shared__ float sh[32][65];
    int conv = blockIdx.y;
    const float* W; __nv_bfloat16* dst; int Kd;
    switch (conv) {
        case 0:  W = Wxr; dst = g_Btx;                     Kd = KX; break;
        case 1:  W = Wxz; dst = g_Btx + (size_t)64 * KX;   Kd = KX; break;
        case 2:  W = Wxn; dst = g_Btx + (size_t)128 * KX;  Kd = KX; break;
        case 3:  W = Whr; dst = g_Bth;                     Kd = KH; break;
        default: W = Whz; dst = g_Bth + (size_t)64 * KH;   Kd = KH; break;
    }
    int k0 = blockIdx.x * 32;
    if (k0 >= Kd) return;
    int tid = threadIdx.x;
#pragma unroll
    for (int w = 0; w < 8; w++) {
        int idx = w * 256 + tid, kk = idx >> 6, c = idx & 63;
        sh[kk][c] = W[(size_t)(k0 + kk) * 64 + c];
    }
    __syncthreads();
#pragma unroll
    for (int w = 0; w < 8; w++) {
        int idx = w * 256 + tid, c = idx >> 5, kk = idx & 31;
        dst[(size_t)c * Kd + k0 + kk] = __float2bfloat16(sh[kk][c]);
    }
}

// ---------------- kernel 6: bf16 mma.sync GEMM ----------------
// BM=64, BK=32 (bf16), 256 threads = 8 warps (2M x 4N), 4-stage cp.async pipeline.
// Smem rows padded to 80B: 16B-aligned cp.async, conflict-free fragment LDS.
#define STAGE 20480
#define NSTG  4

template<int NG>
__device__ __forceinline__ void gemm_body(const __nv_bfloat16* __restrict__ A,
                                          const __nv_bfloat16* __restrict__ Bt,
                                          int Kd, int kc0, int row0,
                                          int pbase, int pstride, uint32_t sb) {
    const int NT = NG * 2;                       // 8-wide N subtiles per warp
    int t = threadIdx.x;
    int w = t >> 5, lane = t & 31;
    int wm = w & 1, wn = w >> 1;
    int gid = lane >> 2, tig = lane & 3;

    float acc[2][NT][4];
#pragma unroll
    for (int mt = 0; mt < 2; mt++)
#pragma unroll
        for (int nt = 0; nt < NT; nt++)
#pragma unroll
            for (int q = 0; q < 4; q++) acc[mt][nt][q] = 0.0f;

    auto ldchunk = [&](int kc, int s) {
        uint32_t Ab = sb + s * STAGE;
        uint32_t Bb = Ab + 5120;
        int kb = kc * 32;
        {   // A: 64 rows x 64B = 256 x 16B, one per thread
            int row = t >> 2, c4 = t & 3;
            int m = row0 + row;
            int mc = m < Nn ? m : 0;
            cpasync16(Ab + (uint32_t)(row * 80 + c4 * 16),
                      A + (size_t)mc * Kd + kb + c4 * 8, m < Nn ? 16 : 0);
        }
#pragma unroll
        for (int q = 0; q < NG; q++) {           // B: NG*64 rows x 64B
            int idx = q * 256 + t, row = idx >> 2, c4 = idx & 3;
            cpasync16(Bb + (uint32_t)(row * 80 + c4 * 16),
                      Bt + (size_t)row * Kd + kb + c4 * 8, 16);
        }
        CP_COMMIT();
    };

    auto compute = [&](int s) {
        uint32_t Ab = sb + s * STAGE;
        uint32_t Bb = Ab + 5120;
#pragma unroll
        for (int ks = 0; ks < 2; ks++) {         // two k16 steps per 32-wide chunk
            uint32_t af[2][4];
#pragma unroll
            for (int mt = 0; mt < 2; mt++) {
                uint32_t base = Ab + (uint32_t)((wm * 32 + mt * 16 + gid) * 80 +
                                                ks * 32 + tig * 4);
                af[mt][0] = lds32(base);            // (row g,   k 2tig..+1)
                af[mt][1] = lds32(base + 8 * 80);   // (row g+8)
                af[mt][2] = lds32(base + 16);       // (row g,   k+8)
                af[mt][3] = lds32(base + 8 * 80 + 16);
            }
#pragma unroll
            for (int nt = 0; nt < NT; nt++) {
                uint32_t bb = Bb + (uint32_t)((wn * NT * 8 + nt * 8 + gid) * 80 +
                                              ks * 32 + tig * 4);
                uint32_t b0 = lds32(bb);            // B[n=gid][k 2tig..+1]
                uint32_t b1 = lds32(bb + 16);       // k+8
#pragma unroll
                for (int mt = 0; mt < 2; mt++)
                    mma16(acc[mt][nt], af[mt], b0, b1);
            }
        }
    };

    ldchunk(kc0, 0);
    ldchunk(kc0 + 1, 1);
    ldchunk(kc0 + 2, 2);
#pragma unroll 1
    for (int i = 0; i < 125; i++) {
        WAITG(2);
        __syncthreads();
        if (i + 3 < 125) ldchunk(kc0 + i + 3, (i + 3) & 3);
        else             CP_COMMIT();            // keep group count uniform for WAITG
        compute(i & 3);
    }

    // epilogue: c0,c1 -> (row g, cols 2tig,2tig+1); c2,c3 -> row g+8
#pragma unroll
    for (int mt = 0; mt < 2; mt++)
#pragma unroll
        for (int nt = 0; nt < NT; nt++) {
            int gcol = wn * NT * 8 + nt * 8 + tig * 2;
            int g = gcol >> 6, cc = gcol & 63;
            float* O = g_part[pbase + g * pstride];
            int r = row0 + wm * 32 + mt * 16 + gid;
            if (r < Nn)
                *(float2*)&O[(size_t)r * 64 + cc] =
                    make_float2(acc[mt][nt][0], acc[mt][nt][1]);
            if (r + 8 < Nn)
                *(float2*)&O[(size_t)(r + 8) * 64 + cc] =
                    make_float2(acc[mt][nt][2], acc[mt][nt][3]);
        }
}

// grid = 282: blocks [0,188) h-pass (94 M-tiles x 2 K-halves), [188,282) x-pass.
__global__ void __launch_bounds__(256, 2) k_gemm_mma() {
    extern __shared__ char smem[];
    uint32_t sb = smem_u32(smem);
    int bx = blockIdx.x;
    if (bx < 188) {
        int mt = bx >> 1, half = bx & 1;
        gemm_body<2>(g_Th, g_Bth, KH, half * 125, mt * 64, 3 + half, 2, sb);
    } else {
        gemm_body<3>(g_Tx, g_Btx, KX, 0, (bx - 188) * 64, 0, 1, sb);
    }
}

// ---------------- kernel 7: root GEMVs (fp32) + bias + GRU gates ----------------
__global__ void k_gates(const float* __restrict__ x, const float* __restrict__ hidden,
                        const float* __restrict__ Rxr, const float* __restrict__ Bxr,
                        const float* __restrict__ Rxz, const float* __restrict__ Bxz,
                        const float* __restrict__ Rxn, const float* __restrict__ Bxn,
                        const float* __restrict__ Rhr, const float* __restrict__ Bhr,
                        const float* __restrict__ Rhz, const float* __restrict__ Bhz,
                        float* __restrict__ out) {
    __shared__ float xs[4][32];
    __shared__ float hs[4][64];
    int tid = threadIdx.x;
    int nb = blockIdx.x * 4;
    if (tid < 128) {
        int nl = tid >> 5, i = tid & 31, n = nb + nl;
        xs[nl][i] = (n < Nn) ? x[n * 32 + i] : 0.f;
    }
    {
        int nl = tid >> 6, c = tid & 63, n = nb + nl;
        hs[nl][c] = (n < Nn) ? hidden[n * 64 + c] : 0.f;
    }
    __syncthreads();
    int nl = tid >> 6, c = tid & 63, n = nb + nl;
    if (n >= Nn) return;
    size_t i = (size_t)n * 64 + c;
    float xr = g_part[0][i] + Bxr[c];
    float xz = g_part[1][i] + Bxz[c];
    float xn = g_part[2][i] + Bxn[c];
    float hr = g_part[3][i] + g_part[4][i] + Bhr[c];
    float hz = g_part[5][i] + g_part[6][i] + Bhz[c];
#pragma unroll 8
    for (int k = 0; k < 32; k++) {
        float xv = xs[nl][k];
        xr += xv * Rxr[k * 64 + c];
        xz += xv * Rxz[k * 64 + c];
        xn += xv * Rxn[k * 64 + c];
    }
#pragma unroll 8
    for (int k = 0; k < 64; k++) {
        float hv = hs[nl][k];
        hr += hv * Rhr[k * 64 + c];
        hz += hv * Rhz[k * 64 + c];
    }
    float r = 1.0f / (1.0f + expf(-(xr + hr)));
    float z = 1.0f / (1.0f + expf(-(xz + hz)));
    float nno = tanhf(xn + r * hr);                 // faithful hr reuse
    out[i] = (1.0f - z) * nno + z * hs[nl][c];
}

// ---------------- launch ----------------
extern "C" void kernel_launch(void* const* d_in, const int* in_sizes, int n_in,
                              void* d_out, int out_size) {
    const float* x      = (const float*)d_in[0];
    const float* hidden = (const float*)d_in[1];
    const int*   ei     = (const int*)d_in[2];
    const float* attr   = (const float*)d_in[3];
    const float* Wxr = (const float*)d_in[4];
    const float* Rxr = (const float*)d_in[5];
    const float* Bxr = (const float*)d_in[6];
    const float* Whr = (const float*)d_in[7];
    const float* Rhr = (const float*)d_in[8];
    const float* Bhr = (const float*)d_in[9];
    const float* Wxz = (const float*)d_in[10];
    const float* Rxz = (const float*)d_in[11];
    const float* Bxz = (const float*)d_in[12];
    const float* Whz = (const float*)d_in[13];
    const float* Rhz = (const float*)d_in[14];
    const float* Bhz = (const float*)d_in[15];
    const float* Wxn = (const float*)d_in[16];
    const float* Rxn = (const float*)d_in[17];
    const float* Bxn = (const float*)d_in[18];
    // d_in[19..21] (W_hn/root_hn/b_hn) are dead in the reference.
    float* out = (float*)d_out;
    (void)in_sizes; (void)n_in; (void)out_size;

    cudaFuncSetAttribute(k_gemm_mma, cudaFuncAttributeMaxDynamicSharedMemorySize,
                         NSTG * STAGE);

    k_zero<<<(Nn + 255) / 256, 256>>>();
    k_edge<<<(Ee + 255) / 256, 256>>>(attr, ei);
    k_scan<<<1, 1024>>>();
    k_fill<<<(Ee + 255) / 256, 256>>>(ei);
    k_scatter<<<Nn, 96>>>(x, hidden, ei);
    k_transpose<<<dim3(250, 5), 256>>>(Wxr, Wxz, Wxn, Whr, Whz);
    k_gemm_mma<<<282, 256, NSTG * STAGE>>>();
    k_gates<<<(Nn + 3) / 4, 256>>>(x, hidden, Rxr, Bxr, Rxz, Bxz, Rxn, Bxn,
                                   Rhr, Bhr, Rhz, Bhz, out);
}

// round 13
// speedup vs baseline: 1.3285x; 1.3285x over previous
#include <cuda_runtime.h>
#include <cuda_bf16.h>
#include <math.h>
#include <stdint.h>

#define Nn   6000
#define Ee   192000
#define CINc 32
#define CHID 64
#define Kk   125
#define KX   4000        // Kk*CINc
#define KH   8000        // Kk*CHID

// ---------------- device scratch ----------------
__device__ __nv_bfloat16 g_Tx[(size_t)Nn * KX];   // bf16, pre-scaled by 1/deg
__device__ __nv_bfloat16 g_Th[(size_t)Nn * KH];
__device__ __nv_bfloat16 g_Btx[192 * KX];         // [co,k]: {Wxr,Wxz,Wxn} transposed
__device__ __nv_bfloat16 g_Bth[128 * KH];         // [co,k]: {Whr,Whz} transposed
__device__ float g_part[7][Nn * CHID];            // 0=XR 1=XZ 2=XN 3,4=HR halves 5,6=HZ halves
__device__ int   g_deg[Nn];
__device__ int   g_fill[Nn];
__device__ int   g_rowstart[Nn + 1];
__device__ int   g_srcs[Ee];                      // CSR-ordered source node ids
__device__ int   g_bidx[Ee * 8];                  // CSR-ordered corner indices
__device__ float g_bval[Ee * 8];                  // CSR-ordered basis weights

// ---------------- PTX helpers (compute_103-safe: sm_80+ features only) ----------------
__device__ __forceinline__ uint32_t smem_u32(const void* p) {
    uint32_t a;
    asm("{ .reg .u64 t; cvta.to.shared.u64 t, %1; cvt.u32.u64 %0, t; }" : "=r"(a) : "l"(p));
    return a;
}
__device__ __forceinline__ void cpasync16(uint32_t dst, const void* src, int src_bytes) {
    asm volatile("cp.async.cg.shared.global [%0], [%1], 16, %2;"
                 :: "r"(dst), "l"(src), "r"(src_bytes) : "memory");
}
#define CP_COMMIT() asm volatile("cp.async.commit_group;" ::: "memory")
#define WAITG(n)    asm volatile("cp.async.wait_group " #n ";" ::: "memory")

__device__ __forceinline__ uint32_t lds32(uint32_t a) {
    uint32_t v;
    asm volatile("ld.shared.b32 %0, [%1];" : "=r"(v) : "r"(a));
    return v;
}
__device__ __forceinline__ void mma16(float* d, const uint32_t* a, uint32_t b0, uint32_t b1) {
    asm volatile(
        "mma.sync.aligned.m16n8k16.row.col.f32.bf16.bf16.f32 "
        "{%0,%1,%2,%3}, {%4,%5,%6,%7}, {%8,%9}, {%0,%1,%2,%3};"
        : "+f"(d[0]), "+f"(d[1]), "+f"(d[2]), "+f"(d[3])
        : "r"(a[0]), "r"(a[1]), "r"(a[2]), "r"(a[3]), "r"(b0), "r"(b1));
}

// ---------------- kernel 0: zero per-call counters ----------------
__global__ void k_zero() {
    int i = blockIdx.x * blockDim.x + threadIdx.x;
    if (i < Nn) { g_deg[i] = 0; g_fill[i] = 0; }
}

// ---------------- kernel 1: degree histogram ----------------
__global__ void k_count(const int* __restrict__ ei) {
    int e = blockIdx.x * blockDim.x + threadIdx.x;
    if (e < Ee) atomicAdd(&g_deg[ei[Ee + e]], 1);
}

// ---------------- kernel 2: exclusive scan (single block) ----------------
__global__ void k_scan() {
    __shared__ int sh[1024];
    int tid = threadIdx.x;
    const int CH = 6;
    int base = tid * CH;
    int local[CH];
    int sum = 0;
#pragma unroll
    for (int q = 0; q < CH; q++) {
        int i = base + q;
        int v = (i < Nn) ? g_deg[i] : 0;
        local[q] = sum;
        sum += v;
    }
    sh[tid] = sum;
    __syncthreads();
    for (int off = 1; off < 1024; off <<= 1) {
        int v = 0;
        if (tid >= off) v = sh[tid - off];
        __syncthreads();
        sh[tid] += v;
        __syncthreads();
    }
    int excl = (tid > 0) ? sh[tid - 1] : 0;
#pragma unroll
    for (int q = 0; q < CH; q++) {
        int i = base + q;
        if (i < Nn) g_rowstart[i] = excl + local[q];
    }
    if (tid == 1023) g_rowstart[Nn] = sh[1023];
}

// ---------------- kernel 3: per-edge basis, written directly in CSR order ----------------
__global__ void k_edge(const float* __restrict__ attr, const int* __restrict__ ei) {
    int e = blockIdx.x * blockDim.x + threadIdx.x;
    if (e >= Ee) return;
    float fr[3]; int i0[3];
#pragma unroll
    for (int d = 0; d < 3; d++) {
        float u = attr[e * 3 + d] * 4.0f;
        int i = (int)floorf(u);
        i = i < 0 ? 0 : (i > 3 ? 3 : i);
        fr[d] = u - (float)i;
        i0[d] = i;
    }
    int dst = ei[Ee + e];
    int p = atomicAdd(&g_fill[dst], 1);
    int slot = g_rowstart[dst] + p;
    g_srcs[slot] = ei[e];
    int4   idx[2];
    float4 val[2];
#pragma unroll
    for (int s = 0; s < 8; s++) {
        int b0 = s & 1, b1 = (s >> 1) & 1, b2 = (s >> 2) & 1;
        int id = (i0[0] + b0) * 25 + (i0[1] + b1) * 5 + (i0[2] + b2);
        float w = (b0 ? fr[0] : 1.0f - fr[0]) *
                  (b1 ? fr[1] : 1.0f - fr[1]) *
                  (b2 ? fr[2] : 1.0f - fr[2]);
        ((int*)idx)[s] = id;
        ((float*)val)[s] = w;
    }
    int4*   ip = (int4*)(g_bidx + (size_t)slot * 8);
    float4* vp = (float4*)(g_bval + (size_t)slot * 8);
    ip[0] = idx[0]; ip[1] = idx[1];
    vp[0] = val[0]; vp[1] = val[1];
}

// ---------------- kernel 4: per-node scatter (linear reads, 2x unrolled) ----------------
__global__ __launch_bounds__(96) void k_scatter(const float* __restrict__ x,
                                                const float* __restrict__ hidden) {
    __shared__ float Tsh[Kk * 96];
    int n = blockIdx.x;
    int c = threadIdx.x;
#pragma unroll 5
    for (int k = 0; k < Kk; k++) Tsh[k * 96 + c] = 0.0f;
    int rs = g_rowstart[n], re = g_rowstart[n + 1];
    float inv = 1.0f / (float)max(re - rs, 1);
    __syncthreads();

    int j = rs;
    if ((re - rs) & 1) {                          // odd-edge prologue (branch once)
        int s0 = __ldg(&g_srcs[j]);
        const int4*   bip = (const int4*)(g_bidx + (size_t)j * 8);
        const float4* bvp = (const float4*)(g_bval + (size_t)j * 8);
        int4   ia = __ldg(bip),     ib = __ldg(bip + 1);
        float4 va = __ldg(bvp),     vb = __ldg(bvp + 1);
        float xv = (c < CINc) ? __ldg(&x[s0 * CINc + c])
                              : __ldg(&hidden[s0 * CHID + (c - CINc)]);
        Tsh[ia.x * 96 + c] += va.x * xv;
        Tsh[ia.y * 96 + c] += va.y * xv;
        Tsh[ia.z * 96 + c] += va.z * xv;
        Tsh[ia.w * 96 + c] += va.w * xv;
        Tsh[ib.x * 96 + c] += vb.x * xv;
        Tsh[ib.y * 96 + c] += vb.y * xv;
        Tsh[ib.z * 96 + c] += vb.z * xv;
        Tsh[ib.w * 96 + c] += vb.w * xv;
        j++;
    }
#pragma unroll 1
    for (; j < re; j += 2) {                      // branch-free 2x body: all loads batch
        int s0 = __ldg(&g_srcs[j]);
        int s1 = __ldg(&g_srcs[j + 1]);
        const int4*   bip = (const int4*)(g_bidx + (size_t)j * 8);
        const float4* bvp = (const float4*)(g_bval + (size_t)j * 8);
        int4   ia0 = __ldg(bip),     ib0 = __ldg(bip + 1);
        int4   ia1 = __ldg(bip + 2), ib1 = __ldg(bip + 3);
        float4 va0 = __ldg(bvp),     vb0 = __ldg(bvp + 1);
        float4 va1 = __ldg(bvp + 2), vb1 = __ldg(bvp + 3);
        float xv0, xv1;
        if (c < CINc) {
            xv0 = __ldg(&x[s0 * CINc + c]);
            xv1 = __ldg(&x[s1 * CINc + c]);
        } else {
            xv0 = __ldg(&hidden[s0 * CHID + (c - CINc)]);
            xv1 = __ldg(&hidden[s1 * CHID + (c - CINc)]);
        }
        Tsh[ia0.x * 96 + c] += va0.x * xv0;
        Tsh[ia0.y * 96 + c] += va0.y * xv0;
        Tsh[ia0.z * 96 + c] += va0.z * xv0;
        Tsh[ia0.w * 96 + c] += va0.w * xv0;
        Tsh[ib0.x * 96 + c] += vb0.x * xv0;
        Tsh[ib0.y * 96 + c] += vb0.y * xv0;
        Tsh[ib0.z * 96 + c] += vb0.z * xv0;
        Tsh[ib0.w * 96 + c] += vb0.w * xv0;
        Tsh[ia1.x * 96 + c] += va1.x * xv1;
        Tsh[ia1.y * 96 + c] += va1.y * xv1;
        Tsh[ia1.z * 96 + c] += va1.z * xv1;
        Tsh[ia1.w * 96 + c] += va1.w * xv1;
        Tsh[ib1.x * 96 + c] += vb1.x * xv1;
        Tsh[ib1.y * 96 + c] += vb1.y * xv1;
        Tsh[ib1.z * 96 + c] += vb1.z * xv1;
        Tsh[ib1.w * 96 + c] += vb1.w * xv1;
    }
    __syncthreads();

    if (c < CINc) {
        __nv_bfloat16* o = g_Tx + (size_t)n * KX + c;
#pragma unroll 5
        for (int k = 0; k < Kk; k++) o[k * CINc] = __float2bfloat16(Tsh[k * 96 + c] * inv);
    } else {
        __nv_bfloat16* o = g_Th + (size_t)n * KH + (c - CINc);
#pragma unroll 5
        for (int k = 0; k < Kk; k++) o[k * CHID] = __float2bfloat16(Tsh[k * 96 + c] * inv);
    }
}

// ---------------- kernel 5: transpose W -> Bt [N,K] K-major, bf16 ----------------
__global__ void k_transpose(const float* __restrict__ Wxr, const float* __restrict__ Wxz,
                            const float* __restrict__ Wxn, const float* __restrict__ Whr,
                            const float* __restrict__ Whz) {
    __shared__ float sh[32][65];
    int conv = blockIdx.y;
    const float* W; __nv_bfloat16* dst; int Kd;
    switch (conv) {
        case 0:  W = Wxr; dst = g_Btx;                     Kd = KX; break;
        case 1:  W = Wxz; dst = g_Btx + (size_t)64 * KX;   Kd = KX; break;
        case 2:  W = Wxn; dst = g_Btx + (size_t)128 * KX;  Kd = KX; break;
        case 3:  W = Whr; dst = g_Bth;                     Kd = KH; break;
        default: W = Whz; dst = g_Bth + (size_t)64 * KH;   Kd = KH; break;
    }
    int k0 = blockIdx.x * 32;
    if (k0 >= Kd) return;
    int tid = threadIdx.x;
#pragma unroll
    for (int w = 0; w < 8; w++) {
        int idx = w * 256 + tid, kk = idx >> 6, c = idx & 63;
        sh[kk][c] = W[(size_t)(k0 + kk) * 64 + c];
    }
    __syncthreads();
#pragma unroll
    for (int w = 0; w < 8; w++) {
        int idx = w * 256 + tid, c = idx >> 5, kk = idx & 31;
        dst[(size_t)c * Kd + k0 + kk] = __float2bfloat16(sh[kk][c]);
    }
}

// ---------------- kernel 6: bf16 mma.sync GEMM ----------------
// BM=64, BK=32 (bf16), 256 threads = 8 warps (2M x 4N), 4-stage cp.async pipeline.
// Smem rows padded to 80B: 16B-aligned cp.async, conflict-free fragment LDS.
#define STAGE 20480
#define NSTG  4

template<int NG>
__device__ __forceinline__ void gemm_body(const __nv_bfloat16* __restrict__ A,
                                          const __nv_bfloat16* __restrict__ Bt,
                                          int Kd, int kc0, int row0,
                                          int pbase, int pstride, uint32_t sb) {
    const int NT = NG * 2;                       // 8-wide N subtiles per warp
    int t = threadIdx.x;
    int w = t >> 5, lane = t & 31;
    int wm = w & 1, wn = w >> 1;
    int gid = lane >> 2, tig = lane & 3;

    float acc[2][NT][4];
#pragma unroll
    for (int mt = 0; mt < 2; mt++)
#pragma unroll
        for (int nt = 0; nt < NT; nt++)
#pragma unroll
            for (int q = 0; q < 4; q++) acc[mt][nt][q] = 0.0f;

    auto ldchunk = [&](int kc, int s) {
        uint32_t Ab = sb + s * STAGE;
        uint32_t Bb = Ab + 5120;
        int kb = kc * 32;
        {   // A: 64 rows x 64B = 256 x 16B, one per thread
            int row = t >> 2, c4 = t & 3;
            int m = row0 + row;
            int mc = m < Nn ? m : 0;
            cpasync16(Ab + (uint32_t)(row * 80 + c4 * 16),
                      A + (size_t)mc * Kd + kb + c4 * 8, m < Nn ? 16 : 0);
        }
#pragma unroll
        for (int q = 0; q < NG; q++) {           // B: NG*64 rows x 64B
            int idx = q * 256 + t, row = idx >> 2, c4 = idx & 3;
            cpasync16(Bb + (uint32_t)(row * 80 + c4 * 16),
                      Bt + (size_t)row * Kd + kb + c4 * 8, 16);
        }
        CP_COMMIT();
    };

    auto compute = [&](int s) {
        uint32_t Ab = sb + s * STAGE;
        uint32_t Bb = Ab + 5120;
#pragma unroll
        for (int ks = 0; ks < 2; ks++) {         // two k16 steps per 32-wide chunk
            uint32_t af[2][4];
#pragma unroll
            for (int mt = 0; mt < 2; mt++) {
                uint32_t base = Ab + (uint32_t)((wm * 32 + mt * 16 + gid) * 80 +
                                                ks * 32 + tig * 4);
                af[mt][0] = lds32(base);            // (row g,   k 2tig..+1)
                af[mt][1] = lds32(base + 8 * 80);   // (row g+8)
                af[mt][2] = lds32(base + 16);       // (row g,   k+8)
                af[mt][3] = lds32(base + 8 * 80 + 16);
            }
#pragma unroll
            for (int nt = 0; nt < NT; nt++) {
                uint32_t bb = Bb + (uint32_t)((wn * NT * 8 + nt * 8 + gid) * 80 +
                                              ks * 32 + tig * 4);
                uint32_t b0 = lds32(bb);            // B[n=gid][k 2tig..+1]
                uint32_t b1 = lds32(bb + 16);       // k+8
#pragma unroll
                for (int mt = 0; mt < 2; mt++)
                    mma16(acc[mt][nt], af[mt], b0, b1);
            }
        }
    };

    ldchunk(kc0, 0);
    ldchunk(kc0 + 1, 1);
    ldchunk(kc0 + 2, 2);
#pragma unroll 1
    for (int i = 0; i < 125; i++) {
        WAITG(2);
        __syncthreads();
        if (i + 3 < 125) ldchunk(kc0 + i + 3, (i + 3) & 3);
        else             CP_COMMIT();            // keep group count uniform for WAITG
        compute(i & 3);
    }

    // epilogue: c0,c1 -> (row g, cols 2tig,2tig+1); c2,c3 -> row g+8
#pragma unroll
    for (int mt = 0; mt < 2; mt++)
#pragma unroll
        for (int nt = 0; nt < NT; nt++) {
            int gcol = wn * NT * 8 + nt * 8 + tig * 2;
            int g = gcol >> 6, cc = gcol & 63;
            float* O = g_part[pbase + g * pstride];
            int r = row0 + wm * 32 + mt * 16 + gid;
            if (r < Nn)
                *(float2*)&O[(size_t)r * 64 + cc] =
                    make_float2(acc[mt][nt][0], acc[mt][nt][1]);
            if (r + 8 < Nn)
                *(float2*)&O[(size_t)(r + 8) * 64 + cc] =
                    make_float2(acc[mt][nt][2], acc[mt][nt][3]);
        }
}

// grid = 282: blocks [0,188) h-pass (94 M-tiles x 2 K-halves), [188,282) x-pass.
__global__ void __launch_bounds__(256, 2) k_gemm_mma() {
    extern __shared__ char smem[];
    uint32_t sb = smem_u32(smem);
    int bx = blockIdx.x;
    if (bx < 188) {
        int mt = bx >> 1, half = bx & 1;
        gemm_body<2>(g_Th, g_Bth, KH, half * 125, mt * 64, 3 + half, 2, sb);
    } else {
        gemm_body<3>(g_Tx, g_Btx, KX, 0, (bx - 188) * 64, 0, 1, sb);
    }
}

// ---------------- kernel 7: root GEMVs (fp32) + bias + GRU gates ----------------
__global__ void k_gates(const float* __restrict__ x, const float* __restrict__ hidden,
                        const float* __restrict__ Rxr, const float* __restrict__ Bxr,
                        const float* __restrict__ Rxz, const float* __restrict__ Bxz,
                        const float* __restrict__ Rxn, const float* __restrict__ Bxn,
                        const float* __restrict__ Rhr, const float* __restrict__ Bhr,
                        const float* __restrict__ Rhz, const float* __restrict__ Bhz,
                        float* __restrict__ out) {
    __shared__ float xs[4][32];
    __shared__ float hs[4][64];
    int tid = threadIdx.x;
    int nb = blockIdx.x * 4;
    if (tid < 128) {
        int nl = tid >> 5, i = tid & 31, n = nb + nl;
        xs[nl][i] = (n < Nn) ? x[n * 32 + i] : 0.f;
    }
    {
        int nl = tid >> 6, c = tid & 63, n = nb + nl;
        hs[nl][c] = (n < Nn) ? hidden[n * 64 + c] : 0.f;
    }
    __syncthreads();
    int nl = tid >> 6, c = tid & 63, n = nb + nl;
    if (n >= Nn) return;
    size_t i = (size_t)n * 64 + c;
    float xr = g_part[0][i] + Bxr[c];
    float xz = g_part[1][i] + Bxz[c];
    float xn = g_part[2][i] + Bxn[c];
    float hr = g_part[3][i] + g_part[4][i] + Bhr[c];
    float hz = g_part[5][i] + g_part[6][i] + Bhz[c];
#pragma unroll 8
    for (int k = 0; k < 32; k++) {
        float xv = xs[nl][k];
        xr += xv * Rxr[k * 64 + c];
        xz += xv * Rxz[k * 64 + c];
        xn += xv * Rxn[k * 64 + c];
    }
#pragma unroll 8
    for (int k = 0; k < 64; k++) {
        float hv = hs[nl][k];
        hr += hv * Rhr[k * 64 + c];
        hz += hv * Rhz[k * 64 + c];
    }
    float r = 1.0f / (1.0f + expf(-(xr + hr)));
    float z = 1.0f / (1.0f + expf(-(xz + hz)));
    float nno = tanhf(xn + r * hr);                 // faithful hr reuse
    out[i] = (1.0f - z) * nno + z * hs[nl][c];
}

// ---------------- launch ----------------
extern "C" void kernel_launch(void* const* d_in, const int* in_sizes, int n_in,
                              void* d_out, int out_size) {
    const float* x      = (const float*)d_in[0];
    const float* hidden = (const float*)d_in[1];
    const int*   ei     = (const int*)d_in[2];
    const float* attr   = (const float*)d_in[3];
    const float* Wxr = (const float*)d_in[4];
    const float* Rxr = (const float*)d_in[5];
    const float* Bxr = (const float*)d_in[6];
    const float* Whr = (const float*)d_in[7];
    const float* Rhr = (const float*)d_in[8];
    const float* Bhr = (const float*)d_in[9];
    const float* Wxz = (const float*)d_in[10];
    const float* Rxz = (const float*)d_in[11];
    const float* Bxz = (const float*)d_in[12];
    const float* Whz = (const float*)d_in[13];
    const float* Rhz = (const float*)d_in[14];
    const float* Bhz = (const float*)d_in[15];
    const float* Wxn = (const float*)d_in[16];
    const float* Rxn = (const float*)d_in[17];
    const float* Bxn = (const float*)d_in[18];
    // d_in[19..21] (W_hn/root_hn/b_hn) are dead in the reference.
    float* out = (float*)d_out;
    (void)in_sizes; (void)n_in; (void)out_size;

    cudaFuncSetAttribute(k_gemm_mma, cudaFuncAttributeMaxDynamicSharedMemorySize,
                         NSTG * STAGE);

    k_zero<<<(Nn + 255) / 256, 256>>>();
    k_count<<<(Ee + 255) / 256, 256>>>(ei);
    k_scan<<<1, 1024>>>();
    k_edge<<<(Ee + 255) / 256, 256>>>(attr, ei);
    k_scatter<<<Nn, 96>>>(x, hidden);
    k_transpose<<<dim3(250, 5), 256>>>(Wxr, Wxz, Wxn, Whr, Whz);
    k_gemm_mma<<<282, 256, NSTG * STAGE>>>();
    k_gates<<<(Nn + 3) / 4, 256>>>(x, hidden, Rxr, Bxr, Rxz, Bxz, Rxn, Bxn,
                                   Rhr, Bhr, Rhz, Bhz, out);
}

// round 14
// speedup vs baseline: 1.4382x; 1.0826x over previous
#include <cuda_runtime.h>
#include <cuda_bf16.h>
#include <math.h>
#include <stdint.h>

#define Nn   6000
#define Ee   192000
#define CINc 32
#define CHID 64
#define Kk   125
#define KX   4000        // Kk*CINc
#define KH   8000        // Kk*CHID

// ---------------- device scratch ----------------
__device__ __nv_bfloat16 g_Tx[(size_t)Nn * KX];   // bf16, pre-scaled by 1/deg
__device__ __nv_bfloat16 g_Th[(size_t)Nn * KH];
__device__ __nv_bfloat16 g_Btx[192 * KX];         // [co,k]: {Wxr,Wxz,Wxn} transposed
__device__ __nv_bfloat16 g_Bth[128 * KH];         // [co,k]: {Whr,Whz} transposed
__device__ float g_part[7][Nn * CHID];            // 0=XR 1=XZ 2=XN 3,4=HR halves 5,6=HZ halves
__device__ int   g_deg[Nn];
__device__ int   g_fill[Nn];
__device__ int   g_rowstart[Nn + 1];
__device__ int   g_srcs[Ee];                      // CSR-ordered source node ids
__device__ uint2 g_bidx[Ee];                      // CSR-ordered corner indices, 8 x u8 packed
__device__ float g_bval[Ee * 8];                  // CSR-ordered basis weights

// ---------------- PTX helpers (compute_103-safe: sm_80+ features only) ----------------
__device__ __forceinline__ uint32_t smem_u32(const void* p) {
    uint32_t a;
    asm("{ .reg .u64 t; cvta.to.shared.u64 t, %1; cvt.u32.u64 %0, t; }" : "=r"(a) : "l"(p));
    return a;
}
__device__ __forceinline__ void cpasync16(uint32_t dst, const void* src, int src_bytes) {
    asm volatile("cp.async.cg.shared.global [%0], [%1], 16, %2;"
                 :: "r"(dst), "l"(src), "r"(src_bytes) : "memory");
}
#define CP_COMMIT() asm volatile("cp.async.commit_group;" ::: "memory")
#define WAITG(n)    asm volatile("cp.async.wait_group " #n ";" ::: "memory")

__device__ __forceinline__ uint32_t lds32(uint32_t a) {
    uint32_t v;
    asm volatile("ld.shared.b32 %0, [%1];" : "=r"(v) : "r"(a));
    return v;
}
__device__ __forceinline__ void mma16(float* d, const uint32_t* a, uint32_t b0, uint32_t b1) {
    asm volatile(
        "mma.sync.aligned.m16n8k16.row.col.f32.bf16.bf16.f32 "
        "{%0,%1,%2,%3}, {%4,%5,%6,%7}, {%8,%9}, {%0,%1,%2,%3};"
        : "+f"(d[0]), "+f"(d[1]), "+f"(d[2]), "+f"(d[3])
        : "r"(a[0]), "r"(a[1]), "r"(a[2]), "r"(a[3]), "r"(b0), "r"(b1));
}

// ---------------- kernel 1: fused transpose W -> Bt (bf16, K-major) + counter zero ----------------
// grid (274, 5): x<250 transpose, (y==0 && x>=250) zero g_deg/g_fill.
__global__ void k_prep(const float* __restrict__ Wxr, const float* __restrict__ Wxz,
                       const float* __restrict__ Wxn, const float* __restrict__ Whr,
                       const float* __restrict__ Whz) {
    if (blockIdx.x >= 250) {
        if (blockIdx.y == 0) {
            int i = (blockIdx.x - 250) * 256 + threadIdx.x;
            if (i < Nn) { g_deg[i] = 0; g_fill[i] = 0; }
        }
        return;
    }
    __shared__ float sh[32][65];
    int conv = blockIdx.y;
    const float* W; __nv_bfloat16* dst; int Kd;
    switch (conv) {
        case 0:  W = Wxr; dst = g_Btx;                     Kd = KX; break;
        case 1:  W = Wxz; dst = g_Btx + (size_t)64 * KX;   Kd = KX; break;
        case 2:  W = Wxn; dst = g_Btx + (size_t)128 * KX;  Kd = KX; break;
        case 3:  W = Whr; dst = g_Bth;                     Kd = KH; break;
        default: W = Whz; dst = g_Bth + (size_t)64 * KH;   Kd = KH; break;
    }
    int k0 = blockIdx.x * 32;
    if (k0 >= Kd) return;
    int tid = threadIdx.x;
#pragma unroll
    for (int w = 0; w < 8; w++) {
        int idx = w * 256 + tid, kk = idx >> 6, c = idx & 63;
        sh[kk][c] = W[(size_t)(k0 + kk) * 64 + c];
    }
    __syncthreads();
#pragma unroll
    for (int w = 0; w < 8; w++) {
        int idx = w * 256 + tid, c = idx >> 5, kk = idx & 31;
        dst[(size_t)c * Kd + k0 + kk] = __float2bfloat16(sh[kk][c]);
    }
}

// ---------------- kernel 2: degree histogram ----------------
__global__ void k_count(const int* __restrict__ ei) {
    int e = blockIdx.x * blockDim.x + threadIdx.x;
    if (e < Ee) atomicAdd(&g_deg[ei[Ee + e]], 1);
}

// ---------------- kernel 3: exclusive scan (single block) ----------------
__global__ void k_scan() {
    __shared__ int sh[1024];
    int tid = threadIdx.x;
    const int CH = 6;
    int base = tid * CH;
    int local[CH];
    int sum = 0;
#pragma unroll
    for (int q = 0; q < CH; q++) {
        int i = base + q;
        int v = (i < Nn) ? g_deg[i] : 0;
        local[q] = sum;
        sum += v;
    }
    sh[tid] = sum;
    __syncthreads();
    for (int off = 1; off < 1024; off <<= 1) {
        int v = 0;
        if (tid >= off) v = sh[tid - off];
        __syncthreads();
        sh[tid] += v;
        __syncthreads();
    }
    int excl = (tid > 0) ? sh[tid - 1] : 0;
#pragma unroll
    for (int q = 0; q < CH; q++) {
        int i = base + q;
        if (i < Nn) g_rowstart[i] = excl + local[q];
    }
    if (tid == 1023) g_rowstart[Nn] = sh[1023];
}

// ---------------- kernel 4: per-edge basis, written directly in CSR order ----------------
__global__ void k_edge(const float* __restrict__ attr, const int* __restrict__ ei) {
    int e = blockIdx.x * blockDim.x + threadIdx.x;
    if (e >= Ee) return;
    float fr[3]; int i0[3];
#pragma unroll
    for (int d = 0; d < 3; d++) {
        float u = attr[e * 3 + d] * 4.0f;
        int i = (int)floorf(u);
        i = i < 0 ? 0 : (i > 3 ? 3 : i);
        fr[d] = u - (float)i;
        i0[d] = i;
    }
    int dst = ei[Ee + e];
    int p = atomicAdd(&g_fill[dst], 1);
    int slot = g_rowstart[dst] + p;
    g_srcs[slot] = ei[e];
    uint32_t lo = 0, hi = 0;
    float4 val[2];
#pragma unroll
    for (int s = 0; s < 8; s++) {
        int b0 = s & 1, b1 = (s >> 1) & 1, b2 = (s >> 2) & 1;
        uint32_t id = (uint32_t)((i0[0] + b0) * 25 + (i0[1] + b1) * 5 + (i0[2] + b2));
        float w = (b0 ? fr[0] : 1.0f - fr[0]) *
                  (b1 ? fr[1] : 1.0f - fr[1]) *
                  (b2 ? fr[2] : 1.0f - fr[2]);
        if (s < 4) lo |= id << (8 * s);
        else       hi |= id << (8 * (s - 4));
        ((float*)val)[s] = w;
    }
    g_bidx[slot] = make_uint2(lo, hi);
    float4* vp = (float4*)(g_bval + (size_t)slot * 8);
    vp[0] = val[0]; vp[1] = val[1];
}

// ---------------- kernel 5: per-node scatter (linear reads, packed idx, 4x unrolled) ----------------
__global__ __launch_bounds__(96) void k_scatter(const float* __restrict__ x,
                                                const float* __restrict__ hidden) {
    __shared__ float Tsh[Kk * 96];
    int n = blockIdx.x;
    int c = threadIdx.x;
#pragma unroll 5
    for (int k = 0; k < Kk; k++) Tsh[k * 96 + c] = 0.0f;
    int rs = g_rowstart[n], re = g_rowstart[n + 1];
    float inv = 1.0f / (float)max(re - rs, 1);
    __syncthreads();

    // hoist x-vs-hidden source select (uniform per thread)
    const float* fb;
    int fstride;
    if (c < CINc) { fb = x + c;                fstride = CINc; }
    else          { fb = hidden + (c - CINc);  fstride = CHID; }

    int j = rs;
    int head = (re - rs) & 3;
    for (int q = 0; q < head; q++, j++) {        // <=3 singles to align main loop
        int s0 = __ldg(&g_srcs[j]);
        uint2 pi = __ldg(&g_bidx[j]);
        const float4* bvp = (const float4*)(g_bval + (size_t)j * 8);
        float4 va = __ldg(bvp), vb = __ldg(bvp + 1);
        float xv = __ldg(&fb[(size_t)s0 * fstride]);
        Tsh[(pi.x & 0xFF) * 96 + c]         += va.x * xv;
        Tsh[((pi.x >> 8) & 0xFF) * 96 + c]  += va.y * xv;
        Tsh[((pi.x >> 16) & 0xFF) * 96 + c] += va.z * xv;
        Tsh[(pi.x >> 24) * 96 + c]          += va.w * xv;
        Tsh[(pi.y & 0xFF) * 96 + c]         += vb.x * xv;
        Tsh[((pi.y >> 8) & 0xFF) * 96 + c]  += vb.y * xv;
        Tsh[((pi.y >> 16) & 0xFF) * 96 + c] += vb.z * xv;
        Tsh[(pi.y >> 24) * 96 + c]          += vb.w * xv;
    }
#pragma unroll 1
    for (; j < re; j += 4) {                     // branch-free 4x body: all loads batch
        int    srcv[4];
        uint2  piv[4];
        float4 vav[4], vbv[4];
        float  xvv[4];
#pragma unroll
        for (int q = 0; q < 4; q++) {
            srcv[q] = __ldg(&g_srcs[j + q]);
            piv[q]  = __ldg(&g_bidx[j + q]);
            const float4* bvp = (const float4*)(g_bval + (size_t)(j + q) * 8);
            vav[q] = __ldg(bvp);
            vbv[q] = __ldg(bvp + 1);
        }
#pragma unroll
        for (int q = 0; q < 4; q++)
            xvv[q] = __ldg(&fb[(size_t)srcv[q] * fstride]);
#pragma unroll
        for (int q = 0; q < 4; q++) {
            uint2 pi = piv[q];
            float4 va = vav[q], vb = vbv[q];
            float xv = xvv[q];
            Tsh[(pi.x & 0xFF) * 96 + c]         += va.x * xv;
            Tsh[((pi.x >> 8) & 0xFF) * 96 + c]  += va.y * xv;
            Tsh[((pi.x >> 16) & 0xFF) * 96 + c] += va.z * xv;
            Tsh[(pi.x >> 24) * 96 + c]          += va.w * xv;
            Tsh[(pi.y & 0xFF) * 96 + c]         += vb.x * xv;
            Tsh[((pi.y >> 8) & 0xFF) * 96 + c]  += vb.y * xv;
            Tsh[((pi.y >> 16) & 0xFF) * 96 + c] += vb.z * xv;
            Tsh[(pi.y >> 24) * 96 + c]          += vb.w * xv;
        }
    }
    __syncthreads();

    if (c < CINc) {
        __nv_bfloat16* o = g_Tx + (size_t)n * KX + c;
#pragma unroll 5
        for (int k = 0; k < Kk; k++) o[k * CINc] = __float2bfloat16(Tsh[k * 96 + c] * inv);
    } else {
        __nv_bfloat16* o = g_Th + (size_t)n * KH + (c - CINc);
#pragma unroll 5
        for (int k = 0; k < Kk; k++) o[k * CHID] = __float2bfloat16(Tsh[k * 96 + c] * inv);
    }
}

// ---------------- kernel 6: bf16 mma.sync GEMM ----------------
// BM=64, BK=32 (bf16), 256 threads = 8 warps (2M x 4N), 4-stage cp.async pipeline.
// Smem rows padded to 80B: 16B-aligned cp.async, conflict-free fragment LDS.
#define STAGE 20480
#define NSTG  4

template<int NG>
__device__ __forceinline__ void gemm_body(const __nv_bfloat16* __restrict__ A,
                                          const __nv_bfloat16* __restrict__ Bt,
                                          int Kd, int kc0, int row0,
                                          int pbase, int pstride, uint32_t sb) {
    const int NT = NG * 2;                       // 8-wide N subtiles per warp
    int t = threadIdx.x;
    int w = t >> 5, lane = t & 31;
    int wm = w & 1, wn = w >> 1;
    int gid = lane >> 2, tig = lane & 3;

    float acc[2][NT][4];
#pragma unroll
    for (int mt = 0; mt < 2; mt++)
#pragma unroll
        for (int nt = 0; nt < NT; nt++)
#pragma unroll
            for (int q = 0; q < 4; q++) acc[mt][nt][q] = 0.0f;

    auto ldchunk = [&](int kc, int s) {
        uint32_t Ab = sb + s * STAGE;
        uint32_t Bb = Ab + 5120;
        int kb = kc * 32;
        {   // A: 64 rows x 64B = 256 x 16B, one per thread
            int row = t >> 2, c4 = t & 3;
            int m = row0 + row;
            int mc = m < Nn ? m : 0;
            cpasync16(Ab + (uint32_t)(row * 80 + c4 * 16),
                      A + (size_t)mc * Kd + kb + c4 * 8, m < Nn ? 16 : 0);
        }
#pragma unroll
        for (int q = 0; q < NG; q++) {           // B: NG*64 rows x 64B
            int idx = q * 256 + t, row = idx >> 2, c4 = idx & 3;
            cpasync16(Bb + (uint32_t)(row * 80 + c4 * 16),
                      Bt + (size_t)row * Kd + kb + c4 * 8, 16);
        }
        CP_COMMIT();
    };

    auto compute = [&](int s) {
        uint32_t Ab = sb + s * STAGE;
        uint32_t Bb = Ab + 5120;
#pragma unroll
        for (int ks = 0; ks < 2; ks++) {         // two k16 steps per 32-wide chunk
            uint32_t af[2][4];
#pragma unroll
            for (int mt = 0; mt < 2; mt++) {
                uint32_t base = Ab + (uint32_t)((wm * 32 + mt * 16 + gid) * 80 +
                                                ks * 32 + tig * 4);
                af[mt][0] = lds32(base);            // (row g,   k 2tig..+1)
                af[mt][1] = lds32(base + 8 * 80);   // (row g+8)
                af[mt][2] = lds32(base + 16);       // (row g,   k+8)
                af[mt][3] = lds32(base + 8 * 80 + 16);
            }
#pragma unroll
            for (int nt = 0; nt < NT; nt++) {
                uint32_t bb = Bb + (uint32_t)((wn * NT * 8 + nt * 8 + gid) * 80 +
                                              ks * 32 + tig * 4);
                uint32_t b0 = lds32(bb);            // B[n=gid][k 2tig..+1]
                uint32_t b1 = lds32(bb + 16);       // k+8
#pragma unroll
                for (int mt = 0; mt < 2; mt++)
                    mma16(acc[mt][nt], af[mt], b0, b1);
            }
        }
    };

    ldchunk(kc0, 0);
    ldchunk(kc0 + 1, 1);
    ldchunk(kc0 + 2, 2);
#pragma unroll 1
    for (int i = 0; i < 125; i++) {
        WAITG(2);
        __syncthreads();
        if (i + 3 < 125) ldchunk(kc0 + i + 3, (i + 3) & 3);
        else             CP_COMMIT();            // keep group count uniform for WAITG
        compute(i & 3);
    }

    // epilogue: c0,c1 -> (row g, cols 2tig,2tig+1); c2,c3 -> row g+8
#pragma unroll
    for (int mt = 0; mt < 2; mt++)
#pragma unroll
        for (int nt = 0; nt < NT; nt++) {
            int gcol = wn * NT * 8 + nt * 8 + tig * 2;
            int g = gcol >> 6, cc = gcol & 63;
            float* O = g_part[pbase + g * pstride];
            int r = row0 + wm * 32 + mt * 16 + gid;
            if (r < Nn)
                *(float2*)&O[(size_t)r * 64 + cc] =
                    make_float2(acc[mt][nt][0], acc[mt][nt][1]);
            if (r + 8 < Nn)
                *(float2*)&O[(size_t)(r + 8) * 64 + cc] =
                    make_float2(acc[mt][nt][2], acc[mt][nt][3]);
        }
}

// grid = 282: blocks [0,188) h-pass (94 M-tiles x 2 K-halves), [188,282) x-pass.
__global__ void __launch_bounds__(256, 2) k_gemm_mma() {
    extern __shared__ char smem[];
    uint32_t sb = smem_u32(smem);
    int bx = blockIdx.x;
    if (bx < 188) {
        int mt = bx >> 1, half = bx & 1;
        gemm_body<2>(g_Th, g_Bth, KH, half * 125, mt * 64, 3 + half, 2, sb);
    } else {
        gemm_body<3>(g_Tx, g_Btx, KX, 0, (bx - 188) * 64, 0, 1, sb);
    }
}

// ---------------- kernel 7: root GEMVs (fp32) + bias + GRU gates ----------------
__global__ void k_gates(const float* __restrict__ x, const float* __restrict__ hidden,
                        const float* __restrict__ Rxr, const float* __restrict__ Bxr,
                        const float* __restrict__ Rxz, const float* __restrict__ Bxz,
                        const float* __restrict__ Rxn, const float* __restrict__ Bxn,
                        const float* __restrict__ Rhr, const float* __restrict__ Bhr,
                        const float* __restrict__ Rhz, const float* __restrict__ Bhz,
                        float* __restrict__ out) {
    __shared__ float xs[4][32];
    __shared__ float hs[4][64];
    int tid = threadIdx.x;
    int nb = blockIdx.x * 4;
    if (tid < 128) {
        int nl = tid >> 5, i = tid & 31, n = nb + nl;
        xs[nl][i] = (n < Nn) ? x[n * 32 + i] : 0.f;
    }
    {
        int nl = tid >> 6, c = tid & 63, n = nb + nl;
        hs[nl][c] = (n < Nn) ? hidden[n * 64 + c] : 0.f;
    }
    __syncthreads();
    int nl = tid >> 6, c = tid & 63, n = nb + nl;
    if (n >= Nn) return;
    size_t i = (size_t)n * 64 + c;
    float xr = g_part[0][i] + Bxr[c];
    float xz = g_part[1][i] + Bxz[c];
    float xn = g_part[2][i] + Bxn[c];
    float hr = g_part[3][i] + g_part[4][i] + Bhr[c];
    float hz = g_part[5][i] + g_part[6][i] + Bhz[c];
#pragma unroll 8
    for (int k = 0; k < 32; k++) {
        float xv = xs[nl][k];
        xr += xv * Rxr[k * 64 + c];
        xz += xv * Rxz[k * 64 + c];
        xn += xv * Rxn[k * 64 + c];
    }
#pragma unroll 8
    for (int k = 0; k < 64; k++) {
        float hv = hs[nl][k];
        hr += hv * Rhr[k * 64 + c];
        hz += hv * Rhz[k * 64 + c];
    }
    float r = 1.0f / (1.0f + expf(-(xr + hr)));
    float z = 1.0f / (1.0f + expf(-(xz + hz)));
    float nno = tanhf(xn + r * hr);                 // faithful hr reuse
    out[i] = (1.0f - z) * nno + z * hs[nl][c];
}

// ---------------- launch ----------------
extern "C" void kernel_launch(void* const* d_in, const int* in_sizes, int n_in,
                              void* d_out, int out_size) {
    const float* x      = (const float*)d_in[0];
    const float* hidden = (const float*)d_in[1];
    const int*   ei     = (const int*)d_in[2];
    const float* attr   = (const float*)d_in[3];
    const float* Wxr = (const float*)d_in[4];
    const float* Rxr = (const float*)d_in[5];
    const float* Bxr = (const float*)d_in[6];
    const float* Whr = (const float*)d_in[7];
    const float* Rhr = (const float*)d_in[8];
    const float* Bhr = (const float*)d_in[9];
    const float* Wxz = (const float*)d_in[10];
    const float* Rxz = (const float*)d_in[11];
    const float* Bxz = (const float*)d_in[12];
    const float* Whz = (const float*)d_in[13];
    const float* Rhz = (const float*)d_in[14];
    const float* Bhz = (const float*)d_in[15];
    const float* Wxn = (const float*)d_in[16];
    const float* Rxn = (const float*)d_in[17];
    const float* Bxn = (const float*)d_in[18];
    // d_in[19..21] (W_hn/root_hn/b_hn) are dead in the reference.
    float* out = (float*)d_out;
    (void)in_sizes; (void)n_in; (void)out_size;

    cudaFuncSetAttribute(k_gemm_mma, cudaFuncAttributeMaxDynamicSharedMemorySize,
                         NSTG * STAGE);

    k_prep<<<dim3(274, 5), 256>>>(Wxr, Wxz, Wxn, Whr, Whz);   // transpose + zero
    k_count<<<(Ee + 255) / 256, 256>>>(ei);
    k_scan<<<1, 1024>>>();
    k_edge<<<(Ee + 255) / 256, 256>>>(attr, ei);
    k_scatter<<<Nn, 96>>>(x, hidden);
    k_gemm_mma<<<282, 256, NSTG * STAGE>>>();                 // launch #6 -> ncu window
    k_gates<<<(Nn + 3) / 4, 256>>>(x, hidden, Rxr, Bxr, Rxz, Bxz, Rxn, Bxn,
                                   Rhr, Bhr, Rhz, Bhz, out);
}

// round 15
// speedup vs baseline: 1.5122x; 1.0515x over previous
#include <cuda_runtime.h>
#include <cuda_bf16.h>
#include <math.h>
#include <stdint.h>

#define Nn   6000
#define Ee   192000
#define CINc 32
#define CHID 64
#define Kk   125
#define KX   4000        // Kk*CINc
#define KH   8000        // Kk*CHID

// ---------------- device scratch ----------------
__device__ __nv_bfloat16 g_Tx[(size_t)Nn * KX];   // bf16, pre-scaled by 1/deg
__device__ __nv_bfloat16 g_Th[(size_t)Nn * KH];
__device__ __nv_bfloat16 g_Btx[192 * KX];         // [co,k]: {Wxr,Wxz,Wxn} transposed
__device__ __nv_bfloat16 g_Bth[128 * KH];         // [co,k]: {Whr,Whz} transposed
__device__ float g_part[7][Nn * CHID];            // 0=XR 1=XZ 2=XN 3,4=HR halves 5,6=HZ halves
__device__ int   g_deg[Nn];                       // zeroed by k_scan (for next call)
__device__ int   g_fill[Nn];                      // zeroed by k_scatter (for next call)
__device__ int   g_rowstart[Nn + 1];
__device__ int   g_srcs[Ee];                      // CSR-ordered source node ids
__device__ uint2 g_bidx[Ee];                      // CSR-ordered corner indices, 8 x u8 packed
__device__ float g_bval[Ee * 8];                  // CSR-ordered basis weights

// ---------------- PTX helpers (compute_103-safe: sm_80+ features only) ----------------
__device__ __forceinline__ uint32_t smem_u32(const void* p) {
    uint32_t a;
    asm("{ .reg .u64 t; cvta.to.shared.u64 t, %1; cvt.u32.u64 %0, t; }" : "=r"(a) : "l"(p));
    return a;
}
__device__ __forceinline__ void cpasync16(uint32_t dst, const void* src, int src_bytes) {
    asm volatile("cp.async.cg.shared.global [%0], [%1], 16, %2;"
                 :: "r"(dst), "l"(src), "r"(src_bytes) : "memory");
}
#define CP_COMMIT() asm volatile("cp.async.commit_group;" ::: "memory")
#define WAITG(n)    asm volatile("cp.async.wait_group " #n ";" ::: "memory")

__device__ __forceinline__ void ldsm_x4(uint32_t* r, uint32_t addr) {
    asm volatile("ldmatrix.sync.aligned.m8n8.x4.shared.b16 {%0,%1,%2,%3}, [%4];"
                 : "=r"(r[0]), "=r"(r[1]), "=r"(r[2]), "=r"(r[3]) : "r"(addr));
}
__device__ __forceinline__ void mma16(float* d, const uint32_t* a, uint32_t b0, uint32_t b1) {
    asm volatile(
        "mma.sync.aligned.m16n8k16.row.col.f32.bf16.bf16.f32 "
        "{%0,%1,%2,%3}, {%4,%5,%6,%7}, {%8,%9}, {%0,%1,%2,%3};"
        : "+f"(d[0]), "+f"(d[1]), "+f"(d[2]), "+f"(d[3])
        : "r"(a[0]), "r"(a[1]), "r"(a[2]), "r"(a[3]), "r"(b0), "r"(b1));
}

// ---------------- kernel 1: degree histogram ----------------
__global__ void k_count(const int* __restrict__ ei) {
    int e = blockIdx.x * blockDim.x + threadIdx.x;
    if (e < Ee) atomicAdd(&g_deg[ei[Ee + e]], 1);
}

// ---------------- kernel 2: exclusive scan (single block) + clear g_deg ----------------
__global__ void k_scan() {
    __shared__ int sh[1024];
    int tid = threadIdx.x;
    const int CH = 6;
    int base = tid * CH;
    int local[CH];
    int sum = 0;
#pragma unroll
    for (int q = 0; q < CH; q++) {
        int i = base + q;
        int v = 0;
        if (i < Nn) { v = g_deg[i]; g_deg[i] = 0; }   // read + clear for next call
        local[q] = sum;
        sum += v;
    }
    sh[tid] = sum;
    __syncthreads();
    for (int off = 1; off < 1024; off <<= 1) {
        int v = 0;
        if (tid >= off) v = sh[tid - off];
        __syncthreads();
        sh[tid] += v;
        __syncthreads();
    }
    int excl = (tid > 0) ? sh[tid - 1] : 0;
#pragma unroll
    for (int q = 0; q < CH; q++) {
        int i = base + q;
        if (i < Nn) g_rowstart[i] = excl + local[q];
    }
    if (tid == 1023) g_rowstart[Nn] = sh[1023];
}

// ---------------- kernel 3: per-edge basis, written directly in CSR order ----------------
__global__ void k_edge(const float* __restrict__ attr, const int* __restrict__ ei) {
    int e = blockIdx.x * blockDim.x + threadIdx.x;
    if (e >= Ee) return;
    float fr[3]; int i0[3];
#pragma unroll
    for (int d = 0; d < 3; d++) {
        float u = attr[e * 3 + d] * 4.0f;
        int i = (int)floorf(u);
        i = i < 0 ? 0 : (i > 3 ? 3 : i);
        fr[d] = u - (float)i;
        i0[d] = i;
    }
    int dst = ei[Ee + e];
    int p = atomicAdd(&g_fill[dst], 1);
    int slot = g_rowstart[dst] + p;
    g_srcs[slot] = ei[e];
    uint32_t lo = 0, hi = 0;
    float4 val[2];
#pragma unroll
    for (int s = 0; s < 8; s++) {
        int b0 = s & 1, b1 = (s >> 1) & 1, b2 = (s >> 2) & 1;
        uint32_t id = (uint32_t)((i0[0] + b0) * 25 + (i0[1] + b1) * 5 + (i0[2] + b2));
        float w = (b0 ? fr[0] : 1.0f - fr[0]) *
                  (b1 ? fr[1] : 1.0f - fr[1]) *
                  (b2 ? fr[2] : 1.0f - fr[2]);
        if (s < 4) lo |= id << (8 * s);
        else       hi |= id << (8 * (s - 4));
        ((float*)val)[s] = w;
    }
    g_bidx[slot] = make_uint2(lo, hi);
    float4* vp = (float4*)(g_bval + (size_t)slot * 8);
    vp[0] = val[0]; vp[1] = val[1];
}

// ---------------- kernel 4: per-node scatter (linear reads, packed idx, 4x unrolled) ----------------
__global__ __launch_bounds__(96) void k_scatter(const float* __restrict__ x,
                                                const float* __restrict__ hidden) {
    __shared__ float Tsh[Kk * 96];
    int n = blockIdx.x;
    int c = threadIdx.x;
#pragma unroll 5
    for (int k = 0; k < Kk; k++) Tsh[k * 96 + c] = 0.0f;
    int rs = g_rowstart[n], re = g_rowstart[n + 1];
    if (c == 0) g_fill[n] = 0;                    // clear for next call
    float inv = 1.0f / (float)max(re - rs, 1);
    __syncthreads();

    // hoist x-vs-hidden source select (uniform per thread)
    const float* fb;
    int fstride;
    if (c < CINc) { fb = x + c;                fstride = CINc; }
    else          { fb = hidden + (c - CINc);  fstride = CHID; }

    int j = rs;
    int head = (re - rs) & 3;
    for (int q = 0; q < head; q++, j++) {        // <=3 singles to align main loop
        int s0 = __ldg(&g_srcs[j]);
        uint2 pi = __ldg(&g_bidx[j]);
        const float4* bvp = (const float4*)(g_bval + (size_t)j * 8);
        float4 va = __ldg(bvp), vb = __ldg(bvp + 1);
        float xv = __ldg(&fb[(size_t)s0 * fstride]);
        Tsh[(pi.x & 0xFF) * 96 + c]         += va.x * xv;
        Tsh[((pi.x >> 8) & 0xFF) * 96 + c]  += va.y * xv;
        Tsh[((pi.x >> 16) & 0xFF) * 96 + c] += va.z * xv;
        Tsh[(pi.x >> 24) * 96 + c]          += va.w * xv;
        Tsh[(pi.y & 0xFF) * 96 + c]         += vb.x * xv;
        Tsh[((pi.y >> 8) & 0xFF) * 96 + c]  += vb.y * xv;
        Tsh[((pi.y >> 16) & 0xFF) * 96 + c] += vb.z * xv;
        Tsh[(pi.y >> 24) * 96 + c]          += vb.w * xv;
    }
#pragma unroll 1
    for (; j < re; j += 4) {                     // branch-free 4x body: all loads batch
        int    srcv[4];
        uint2  piv[4];
        float4 vav[4], vbv[4];
        float  xvv[4];
#pragma unroll
        for (int q = 0; q < 4; q++) {
            srcv[q] = __ldg(&g_srcs[j + q]);
            piv[q]  = __ldg(&g_bidx[j + q]);
            const float4* bvp = (const float4*)(g_bval + (size_t)(j + q) * 8);
            vav[q] = __ldg(bvp);
            vbv[q] = __ldg(bvp + 1);
        }
#pragma unroll
        for (int q = 0; q < 4; q++)
            xvv[q] = __ldg(&fb[(size_t)srcv[q] * fstride]);
#pragma unroll
        for (int q = 0; q < 4; q++) {
            uint2 pi = piv[q];
            float4 va = vav[q], vb = vbv[q];
            float xv = xvv[q];
            Tsh[(pi.x & 0xFF) * 96 + c]         += va.x * xv;
            Tsh[((pi.x >> 8) & 0xFF) * 96 + c]  += va.y * xv;
            Tsh[((pi.x >> 16) & 0xFF) * 96 + c] += va.z * xv;
            Tsh[(pi.x >> 24) * 96 + c]          += va.w * xv;
            Tsh[(pi.y & 0xFF) * 96 + c]         += vb.x * xv;
            Tsh[((pi.y >> 8) & 0xFF) * 96 + c]  += vb.y * xv;
            Tsh[((pi.y >> 16) & 0xFF) * 96 + c] += vb.z * xv;
            Tsh[(pi.y >> 24) * 96 + c]          += vb.w * xv;
        }
    }
    __syncthreads();

    if (c < CINc) {
        __nv_bfloat16* o = g_Tx + (size_t)n * KX + c;
#pragma unroll 5
        for (int k = 0; k < Kk; k++) o[k * CINc] = __float2bfloat16(Tsh[k * 96 + c] * inv);
    } else {
        __nv_bfloat16* o = g_Th + (size_t)n * KH + (c - CINc);
#pragma unroll 5
        for (int k = 0; k < Kk; k++) o[k * CHID] = __float2bfloat16(Tsh[k * 96 + c] * inv);
    }
}

// ---------------- kernel 5: transpose W -> Bt [N,K] K-major, bf16 ----------------
__global__ void k_transpose(const float* __restrict__ Wxr, const float* __restrict__ Wxz,
                            const float* __restrict__ Wxn, const float* __restrict__ Whr,
                            const float* __restrict__ Whz) {
    __shared__ float sh[32][65];
    int conv = blockIdx.y;
    const float* W; __nv_bfloat16* dst; int Kd;
    switch (conv) {
        case 0:  W = Wxr; dst = g_Btx;                     Kd = KX; break;
        case 1:  W = Wxz; dst = g_Btx + (size_t)64 * KX;   Kd = KX; break;
        case 2:  W = Wxn; dst = g_Btx + (size_t)128 * KX;  Kd = KX; break;
        case 3:  W = Whr; dst = g_Bth;                     Kd = KH; break;
        default: W = Whz; dst = g_Bth + (size_t)64 * KH;   Kd = KH; break;
    }
    int k0 = blockIdx.x * 32;
    if (k0 >= Kd) return;
    int tid = threadIdx.x;
#pragma unroll
    for (int w = 0; w < 8; w++) {
        int idx = w * 256 + tid, kk = idx >> 6, c = idx & 63;
        sh[kk][c] = W[(size_t)(k0 + kk) * 64 + c];
    }
    __syncthreads();
#pragma unroll
    for (int w = 0; w < 8; w++) {
        int idx = w * 256 + tid, c = idx >> 5, kk = idx & 31;
        dst[(size_t)c * Kd + k0 + kk] = __float2bfloat16(sh[kk][c]);
    }
}

// ---------------- kernel 6: bf16 mma.sync GEMM (ldmatrix fragments) ----------------
// BM=64, BK=32 (bf16), 256 threads = 8 warps (2M x 4N), 4-stage cp.async pipeline.
// Smem rows padded to 80B: 16B cp.async alignment; 8 LDSM rows at word offsets
// {0,20,8,28,16,4,24,12} mod 32 -> all banks covered, conflict-free.
#define STAGE 20480
#define NSTG  4

template<int NG>
__device__ __forceinline__ void gemm_body(const __nv_bfloat16* __restrict__ A,
                                          const __nv_bfloat16* __restrict__ Bt,
                                          int Kd, int kc0, int row0,
                                          int pbase, int pstride, uint32_t sb) {
    const int NT = NG * 2;                       // 8-wide N subtiles per warp
    int t = threadIdx.x;
    int w = t >> 5, lane = t & 31;
    int wm = w & 1, wn = w >> 1;
    int gid = lane >> 2, tig = lane & 3;
    int rlane = lane & 7, q = lane >> 3;         // ldmatrix lane decomposition

    float acc[2][NT][4];
#pragma unroll
    for (int mt = 0; mt < 2; mt++)
#pragma unroll
        for (int nt = 0; nt < NT; nt++)
#pragma unroll
            for (int p = 0; p < 4; p++) acc[mt][nt][p] = 0.0f;

    auto ldchunk = [&](int kc, int s) {
        uint32_t Ab = sb + s * STAGE;
        uint32_t Bb = Ab + 5120;
        int kb = kc * 32;
        {   // A: 64 rows x 64B = 256 x 16B, one per thread
            int row = t >> 2, c4 = t & 3;
            int m = row0 + row;
            int mc = m < Nn ? m : 0;
            cpasync16(Ab + (uint32_t)(row * 80 + c4 * 16),
                      A + (size_t)mc * Kd + kb + c4 * 8, m < Nn ? 16 : 0);
        }
#pragma unroll
        for (int p = 0; p < NG; p++) {           // B: NG*64 rows x 64B
            int idx = p * 256 + t, row = idx >> 2, c4 = idx & 3;
            cpasync16(Bb + (uint32_t)(row * 80 + c4 * 16),
                      Bt + (size_t)row * Kd + kb + c4 * 8, 16);
        }
        CP_COMMIT();
    };

    auto compute = [&](int s) {
        uint32_t Ab = sb + s * STAGE;
        uint32_t Bb = Ab + 5120;
#pragma unroll
        for (int ks = 0; ks < 2; ks++) {         // two k16 steps per 32-wide chunk
            uint32_t af[2][4];
#pragma unroll
            for (int mt = 0; mt < 2; mt++) {
                // matrices: {rows+0 B+0, rows+8 B+0, rows+0 B+16, rows+8 B+16}
                uint32_t addr = Ab + (uint32_t)((wm * 32 + mt * 16 + (q & 1) * 8 + rlane) * 80
                                                + ks * 32 + (q >> 1) * 16);
                ldsm_x4(af[mt], addr);
            }
            uint32_t bf[NG][4];
#pragma unroll
            for (int p = 0; p < NG; p++) {
                // matrices: {n+0 B+0, n+0 B+16, n+8 B+0, n+8 B+16}
                uint32_t addr = Bb + (uint32_t)((wn * NT * 8 + p * 16 + (q >> 1) * 8 + rlane) * 80
                                                + ks * 32 + (q & 1) * 16);
                ldsm_x4(bf[p], addr);
            }
#pragma unroll
            for (int p = 0; p < NG; p++)
#pragma unroll
                for (int h = 0; h < 2; h++)
#pragma unroll
                    for (int mt = 0; mt < 2; mt++)
                        mma16(acc[mt][2 * p + h], af[mt], bf[p][2 * h], bf[p][2 * h + 1]);
        }
    };

    ldchunk(kc0, 0);
    ldchunk(kc0 + 1, 1);
    ldchunk(kc0 + 2, 2);
#pragma unroll 1
    for (int i = 0; i < 125; i++) {
        WAITG(2);
        __syncthreads();
        if (i + 3 < 125) ldchunk(kc0 + i + 3, (i + 3) & 3);
        else             CP_COMMIT();            // keep group count uniform for WAITG
        compute(i & 3);
    }

    // epilogue: c0,c1 -> (row g, cols 2tig,2tig+1); c2,c3 -> row g+8
#pragma unroll
    for (int mt = 0; mt < 2; mt++)
#pragma unroll
        for (int nt = 0; nt < NT; nt++) {
            int gcol = wn * NT * 8 + nt * 8 + tig * 2;
            int g = gcol >> 6, cc = gcol & 63;
            float* O = g_part[pbase + g * pstride];
            int r = row0 + wm * 32 + mt * 16 + gid;
            if (r < Nn)
                *(float2*)&O[(size_t)r * 64 + cc] =
                    make_float2(acc[mt][nt][0], acc[mt][nt][1]);
            if (r + 8 < Nn)
                *(float2*)&O[(size_t)(r + 8) * 64 + cc] =
                    make_float2(acc[mt][nt][2], acc[mt][nt][3]);
        }
}

// grid = 282: blocks [0,188) h-pass (94 M-tiles x 2 K-halves), [188,282) x-pass.
__global__ void __launch_bounds__(256, 2) k_gemm_mma() {
    extern __shared__ char smem[];
    uint32_t sb = smem_u32(smem);
    int bx = blockIdx.x;
    if (bx < 188) {
        int mt = bx >> 1, half = bx & 1;
        gemm_body<2>(g_Th, g_Bth, KH, half * 125, mt * 64, 3 + half, 2, sb);
    } else {
        gemm_body<3>(g_Tx, g_Btx, KX, 0, (bx - 188) * 64, 0, 1, sb);
    }
}

// ---------------- kernel 7: root GEMVs (fp32) + bias + GRU gates ----------------
__global__ void k_gates(const float* __restrict__ x, const float* __restrict__ hidden,
                        const float* __restrict__ Rxr, const float* __restrict__ Bxr,
                        const float* __restrict__ Rxz, const float* __restrict__ Bxz,
                        const float* __restrict__ Rxn, const float* __restrict__ Bxn,
                        const float* __restrict__ Rhr, const float* __restrict__ Bhr,
                        const float* __restrict__ Rhz, const float* __restrict__ Bhz,
                        float* __restrict__ out) {
    __shared__ float xs[4][32];
    __shared__ float hs[4][64];
    int tid = threadIdx.x;
    int nb = blockIdx.x * 4;
    if (tid < 128) {
        int nl = tid >> 5, i = tid & 31, n = nb + nl;
        xs[nl][i] = (n < Nn) ? x[n * 32 + i] : 0.f;
    }
    {
        int nl = tid >> 6, c = tid & 63, n = nb + nl;
        hs[nl][c] = (n < Nn) ? hidden[n * 64 + c] : 0.f;
    }
    __syncthreads();
    int nl = tid >> 6, c = tid & 63, n = nb + nl;
    if (n >= Nn) return;
    size_t i = (size_t)n * 64 + c;
    float xr = g_part[0][i] + Bxr[c];
    float xz = g_part[1][i] + Bxz[c];
    float xn = g_part[2][i] + Bxn[c];
    float hr = g_part[3][i] + g_part[4][i] + Bhr[c];
    float hz = g_part[5][i] + g_part[6][i] + Bhz[c];
#pragma unroll 8
    for (int k = 0; k < 32; k++) {
        float xv = xs[nl][k];
        xr += xv * Rxr[k * 64 + c];
        xz += xv * Rxz[k * 64 + c];
        xn += xv * Rxn[k * 64 + c];
    }
#pragma unroll 8
    for (int k = 0; k < 64; k++) {
        float hv = hs[nl][k];
        hr += hv * Rhr[k * 64 + c];
        hz += hv * Rhz[k * 64 + c];
    }
    float r = 1.0f / (1.0f + expf(-(xr + hr)));
    float z = 1.0f / (1.0f + expf(-(xz + hz)));
    float nno = tanhf(xn + r * hr);                 // faithful hr reuse
    out[i] = (1.0f - z) * nno + z * hs[nl][c];
}

// ---------------- launch ----------------
extern "C" void kernel_launch(void* const* d_in, const int* in_sizes, int n_in,
                              void* d_out, int out_size) {
    const float* x      = (const float*)d_in[0];
    const float* hidden = (const float*)d_in[1];
    const int*   ei     = (const int*)d_in[2];
    const float* attr   = (const float*)d_in[3];
    const float* Wxr = (const float*)d_in[4];
    const float* Rxr = (const float*)d_in[5];
    const float* Bxr = (const float*)d_in[6];
    const float* Whr = (const float*)d_in[7];
    const float* Rhr = (const float*)d_in[8];
    const float* Bhr = (const float*)d_in[9];
    const float* Wxz = (const float*)d_in[10];
    const float* Rxz = (const float*)d_in[11];
    const float* Bxz = (const float*)d_in[12];
    const float* Whz = (const float*)d_in[13];
    const float* Rhz = (const float*)d_in[14];
    const float* Bhz = (const float*)d_in[15];
    const float* Wxn = (const float*)d_in[16];
    const float* Rxn = (const float*)d_in[17];
    const float* Bxn = (const float*)d_in[18];
    // d_in[19..21] (W_hn/root_hn/b_hn) are dead in the reference.
    float* out = (float*)d_out;
    (void)in_sizes; (void)n_in; (void)out_size;

    cudaFuncSetAttribute(k_gemm_mma, cudaFuncAttributeMaxDynamicSharedMemorySize,
                         NSTG * STAGE);

    k_count<<<(Ee + 255) / 256, 256>>>(ei);                   // #1 (g_deg pre-zeroed)
    k_scan<<<1, 1024>>>();                                    // #2 (clears g_deg)
    k_edge<<<(Ee + 255) / 256, 256>>>(attr, ei);              // #3 (g_fill pre-zeroed)
    k_scatter<<<Nn, 96>>>(x, hidden);                         // #4 -> ncu window, clears g_fill
    k_transpose<<<dim3(250, 5), 256>>>(Wxr, Wxz, Wxn, Whr, Whz);
    k_gemm_mma<<<282, 256, NSTG * STAGE>>>();
    k_gates<<<(Nn + 3) / 4, 256>>>(x, hidden, Rxr, Bxr, Rxz, Bxz, Rxn, Bxn,
                                   Rhr, Bhr, Rhz, Bhz, out);
}

// round 16
// speedup vs baseline: 1.5398x; 1.0182x over previous
#include <cuda_runtime.h>
#include <cuda_bf16.h>
#include <math.h>
#include <stdint.h>

#define Nn   6000
#define Ee   192000
#define CINc 32
#define CHID 64
#define Kk   125
#define KX   4000        // Kk*CINc
#define KH   8000        // Kk*CHID

// ---------------- device scratch ----------------
__device__ __nv_bfloat16 g_Tx[(size_t)Nn * KX];   // bf16, pre-scaled by 1/deg
__device__ __nv_bfloat16 g_Th[(size_t)Nn * KH];
__device__ __nv_bfloat16 g_Btx[192 * KX];         // [co,k]: {Wxr,Wxz,Wxn} transposed
__device__ __nv_bfloat16 g_Bth[128 * KH];         // [co,k]: {Whr,Whz} transposed
__device__ float g_part[7][Nn * CHID];            // 0=XR 1=XZ 2=XN 3,4=HR halves 5,6=HZ halves
__device__ int   g_deg[Nn];                       // zeroed by k_scan (for next call)
__device__ int   g_fill[Nn];                      // zeroed by k_scatter (for next call)
__device__ int   g_rowstart[Nn + 1];
__device__ int   g_srcs[Ee];                      // CSR-ordered source node ids
__device__ uint2 g_bidx[Ee];                      // CSR-ordered corner indices, 8 x u8 packed
__device__ float g_bval[Ee * 8];                  // CSR-ordered basis weights

// ---------------- PTX helpers (compute_103-safe: sm_80+ features only) ----------------
__device__ __forceinline__ uint32_t smem_u32(const void* p) {
    uint32_t a;
    asm("{ .reg .u64 t; cvta.to.shared.u64 t, %1; cvt.u32.u64 %0, t; }" : "=r"(a) : "l"(p));
    return a;
}
__device__ __forceinline__ void cpasync16(uint32_t dst, const void* src, int src_bytes) {
    asm volatile("cp.async.cg.shared.global [%0], [%1], 16, %2;"
                 :: "r"(dst), "l"(src), "r"(src_bytes) : "memory");
}
#define CP_COMMIT() asm volatile("cp.async.commit_group;" ::: "memory")
#define WAITG(n)    asm volatile("cp.async.wait_group " #n ";" ::: "memory")

__device__ __forceinline__ void ldsm_x4(uint32_t* r, uint32_t addr) {
    asm volatile("ldmatrix.sync.aligned.m8n8.x4.shared.b16 {%0,%1,%2,%3}, [%4];"
                 : "=r"(r[0]), "=r"(r[1]), "=r"(r[2]), "=r"(r[3]) : "r"(addr));
}
__device__ __forceinline__ void mma16(float* d, const uint32_t* a, uint32_t b0, uint32_t b1) {
    asm volatile(
        "mma.sync.aligned.m16n8k16.row.col.f32.bf16.bf16.f32 "
        "{%0,%1,%2,%3}, {%4,%5,%6,%7}, {%8,%9}, {%0,%1,%2,%3};"
        : "+f"(d[0]), "+f"(d[1]), "+f"(d[2]), "+f"(d[3])
        : "r"(a[0]), "r"(a[1]), "r"(a[2]), "r"(a[3]), "r"(b0), "r"(b1));
}

// ---------------- kernel 1: degree histogram ----------------
__global__ void k_count(const int* __restrict__ ei) {
    int e = blockIdx.x * blockDim.x + threadIdx.x;
    if (e < Ee) atomicAdd(&g_deg[ei[Ee + e]], 1);
}

// ---------------- kernel 2: exclusive scan (single block) + clear g_deg ----------------
__global__ void k_scan() {
    __shared__ int sh[1024];
    int tid = threadIdx.x;
    const int CH = 6;
    int base = tid * CH;
    int local[CH];
    int sum = 0;
#pragma unroll
    for (int q = 0; q < CH; q++) {
        int i = base + q;
        int v = 0;
        if (i < Nn) { v = g_deg[i]; g_deg[i] = 0; }   // read + clear for next call
        local[q] = sum;
        sum += v;
    }
    sh[tid] = sum;
    __syncthreads();
    for (int off = 1; off < 1024; off <<= 1) {
        int v = 0;
        if (tid >= off) v = sh[tid - off];
        __syncthreads();
        sh[tid] += v;
        __syncthreads();
    }
    int excl = (tid > 0) ? sh[tid - 1] : 0;
#pragma unroll
    for (int q = 0; q < CH; q++) {
        int i = base + q;
        if (i < Nn) g_rowstart[i] = excl + local[q];
    }
    if (tid == 1023) g_rowstart[Nn] = sh[1023];
}

// ---------------- kernel 3: per-edge basis, written directly in CSR order ----------------
__global__ void k_edge(const float* __restrict__ attr, const int* __restrict__ ei) {
    int e = blockIdx.x * blockDim.x + threadIdx.x;
    if (e >= Ee) return;
    float fr[3]; int i0[3];
#pragma unroll
    for (int d = 0; d < 3; d++) {
        float u = attr[e * 3 + d] * 4.0f;
        int i = (int)floorf(u);
        i = i < 0 ? 0 : (i > 3 ? 3 : i);
        fr[d] = u - (float)i;
        i0[d] = i;
    }
    int dst = ei[Ee + e];
    int p = atomicAdd(&g_fill[dst], 1);
    int slot = g_rowstart[dst] + p;
    g_srcs[slot] = ei[e];
    uint32_t lo = 0, hi = 0;
    float4 val[2];
#pragma unroll
    for (int s = 0; s < 8; s++) {
        int b0 = s & 1, b1 = (s >> 1) & 1, b2 = (s >> 2) & 1;
        uint32_t id = (uint32_t)((i0[0] + b0) * 25 + (i0[1] + b1) * 5 + (i0[2] + b2));
        float w = (b0 ? fr[0] : 1.0f - fr[0]) *
                  (b1 ? fr[1] : 1.0f - fr[1]) *
                  (b2 ? fr[2] : 1.0f - fr[2]);
        if (s < 4) lo |= id << (8 * s);
        else       hi |= id << (8 * (s - 4));
        ((float*)val)[s] = w;
    }
    g_bidx[slot] = make_uint2(lo, hi);
    float4* vp = (float4*)(g_bval + (size_t)slot * 8);
    vp[0] = val[0]; vp[1] = val[1];
}

// ---------------- kernel 4: per-node scatter, parity-split halves ----------------
// 192 threads = 96 channels x 2 parity halves. Corner offsets {0,25,5,30,1,26,6,31}
// are exactly 4 even + 4 odd, so half h (owning idx with idx&1==h) does exactly
// 4 unconditional RMWs per edge, chosen pairwise by branch-free SELs.
__global__ __launch_bounds__(192) void k_scatter(const float* __restrict__ x,
                                                 const float* __restrict__ hidden) {
    __shared__ float Tsh[Kk * 96];
    int n = blockIdx.x;
    int t = threadIdx.x;
    int c = t % 96, h = t / 96;
    for (int i = t; i < Kk * 96; i += 192) Tsh[i] = 0.0f;
    int rs = g_rowstart[n], re = g_rowstart[n + 1];
    if (t == 0) g_fill[n] = 0;                    // clear for next call
    float inv = 1.0f / (float)max(re - rs, 1);
    __syncthreads();

    // hoist x-vs-hidden source select (uniform per thread)
    const float* fb;
    int fstride;
    if (c < CINc) { fb = x + c;                fstride = CINc; }
    else          { fb = hidden + (c - CINc);  fstride = CHID; }

    // per-edge accumulate: pick this half's 4 corners from the 4 (even,odd) pairs
    auto accum = [&](uint2 pi, float4 va, float4 vb, float xv) {
        int ix0 = pi.x & 0xFF, ix1 = (pi.x >> 8) & 0xFF;
        int ix2 = (pi.x >> 16) & 0xFF, ix3 = pi.x >> 24;
        int ix4 = pi.y & 0xFF, ix5 = (pi.y >> 8) & 0xFF;
        int ix6 = (pi.y >> 16) & 0xFF, ix7 = pi.y >> 24;
        bool e = ((ix0 ^ h) & 1) == 0;            // parity(base) == my half?
        int   ja = e ? ix0 : ix1;  float wa = e ? va.x : va.y;
        int   jb = e ? ix3 : ix2;  float wb = e ? va.w : va.z;
        int   jc = e ? ix5 : ix4;  float wc = e ? vb.y : vb.x;
        int   jd = e ? ix6 : ix7;  float wd = e ? vb.z : vb.w;
        Tsh[ja * 96 + c] += wa * xv;
        Tsh[jb * 96 + c] += wb * xv;
        Tsh[jc * 96 + c] += wc * xv;
        Tsh[jd * 96 + c] += wd * xv;
    };

    int j = rs;
    int head = (re - rs) & 3;
    for (int q = 0; q < head; q++, j++) {        // <=3 singles to align main loop
        int s0 = __ldg(&g_srcs[j]);
        uint2 pi = __ldg(&g_bidx[j]);
        const float4* bvp = (const float4*)(g_bval + (size_t)j * 8);
        float4 va = __ldg(bvp), vb = __ldg(bvp + 1);
        float xv = __ldg(&fb[(size_t)s0 * fstride]);
        accum(pi, va, vb, xv);
    }
#pragma unroll 1
    for (; j < re; j += 4) {                     // branch-free 4x body: all loads batch
        int    srcv[4];
        uint2  piv[4];
        float4 vav[4], vbv[4];
        float  xvv[4];
#pragma unroll
        for (int q = 0; q < 4; q++) {
            srcv[q] = __ldg(&g_srcs[j + q]);
            piv[q]  = __ldg(&g_bidx[j + q]);
            const float4* bvp = (const float4*)(g_bval + (size_t)(j + q) * 8);
            vav[q] = __ldg(bvp);
            vbv[q] = __ldg(bvp + 1);
        }
#pragma unroll
        for (int q = 0; q < 4; q++)
            xvv[q] = __ldg(&fb[(size_t)srcv[q] * fstride]);
#pragma unroll
        for (int q = 0; q < 4; q++)
            accum(piv[q], vav[q], vbv[q], xvv[q]);
    }
    __syncthreads();

    // writeout: half 0 -> k [0,63), half 1 -> k [63,125)
    int k0 = h ? 63 : 0, k1 = h ? 125 : 63;
    if (c < CINc) {
        __nv_bfloat16* o = g_Tx + (size_t)n * KX + c;
        for (int k = k0; k < k1; k++) o[k * CINc] = __float2bfloat16(Tsh[k * 96 + c] * inv);
    } else {
        __nv_bfloat16* o = g_Th + (size_t)n * KH + (c - CINc);
        for (int k = k0; k < k1; k++) o[k * CHID] = __float2bfloat16(Tsh[k * 96 + c] * inv);
    }
}

// ---------------- kernel 5: transpose W -> Bt [N,K] K-major, bf16 ----------------
__global__ void k_transpose(const float* __restrict__ Wxr, const float* __restrict__ Wxz,
                            const float* __restrict__ Wxn, const float* __restrict__ Whr,
                            const float* __restrict__ Whz) {
    __shared__ float sh[32][65];
    int conv = blockIdx.y;
    const float* W; __nv_bfloat16* dst; int Kd;
    switch (conv) {
        case 0:  W = Wxr; dst = g_Btx;                     Kd = KX; break;
        case 1:  W = Wxz; dst = g_Btx + (size_t)64 * KX;   Kd = KX; break;
        case 2:  W = Wxn; dst = g_Btx + (size_t)128 * KX;  Kd = KX; break;
        case 3:  W = Whr; dst = g_Bth;                     Kd = KH; break;
        default: W = Whz; dst = g_Bth + (size_t)64 * KH;   Kd = KH; break;
    }
    int k0 = blockIdx.x * 32;
    if (k0 >= Kd) return;
    int tid = threadIdx.x;
#pragma unroll
    for (int w = 0; w < 8; w++) {
        int idx = w * 256 + tid, kk = idx >> 6, c = idx & 63;
        sh[kk][c] = W[(size_t)(k0 + kk) * 64 + c];
    }
    __syncthreads();
#pragma unroll
    for (int w = 0; w < 8; w++) {
        int idx = w * 256 + tid, c = idx >> 5, kk = idx & 31;
        dst[(size_t)c * Kd + k0 + kk] = __float2bfloat16(sh[kk][c]);
    }
}

// ---------------- kernel 6: bf16 mma.sync GEMM (ldmatrix fragments) ----------------
// BM=64, BK=32 (bf16), 256 threads = 8 warps (2M x 4N), 4-stage cp.async pipeline.
// Smem rows padded to 80B: 16B cp.async alignment; 8 LDSM rows at word offsets
// {0,20,8,28,16,4,24,12} mod 32 -> all banks covered, conflict-free.
#define STAGE 20480
#define NSTG  4

template<int NG>
__device__ __forceinline__ void gemm_body(const __nv_bfloat16* __restrict__ A,
                                          const __nv_bfloat16* __restrict__ Bt,
                                          int Kd, int kc0, int row0,
                                          int pbase, int pstride, uint32_t sb) {
    const int NT = NG * 2;                       // 8-wide N subtiles per warp
    int t = threadIdx.x;
    int w = t >> 5, lane = t & 31;
    int wm = w & 1, wn = w >> 1;
    int gid = lane >> 2, tig = lane & 3;
    int rlane = lane & 7, q = lane >> 3;         // ldmatrix lane decomposition

    float acc[2][NT][4];
#pragma unroll
    for (int mt = 0; mt < 2; mt++)
#pragma unroll
        for (int nt = 0; nt < NT; nt++)
#pragma unroll
            for (int p = 0; p < 4; p++) acc[mt][nt][p] = 0.0f;

    auto ldchunk = [&](int kc, int s) {
        uint32_t Ab = sb + s * STAGE;
        uint32_t Bb = Ab + 5120;
        int kb = kc * 32;
        {   // A: 64 rows x 64B = 256 x 16B, one per thread
            int row = t >> 2, c4 = t & 3;
            int m = row0 + row;
            int mc = m < Nn ? m : 0;
            cpasync16(Ab + (uint32_t)(row * 80 + c4 * 16),
                      A + (size_t)mc * Kd + kb + c4 * 8, m < Nn ? 16 : 0);
        }
#pragma unroll
        for (int p = 0; p < NG; p++) {           // B: NG*64 rows x 64B
            int idx = p * 256 + t, row = idx >> 2, c4 = idx & 3;
            cpasync16(Bb + (uint32_t)(row * 80 + c4 * 16),
                      Bt + (size_t)row * Kd + kb + c4 * 8, 16);
        }
        CP_COMMIT();
    };

    auto compute = [&](int s) {
        uint32_t Ab = sb + s * STAGE;
        uint32_t Bb = Ab + 5120;
#pragma unroll
        for (int ks = 0; ks < 2; ks++) {         // two k16 steps per 32-wide chunk
            uint32_t af[2][4];
#pragma unroll
            for (int mt = 0; mt < 2; mt++) {
                // matrices: {rows+0 B+0, rows+8 B+0, rows+0 B+16, rows+8 B+16}
                uint32_t addr = Ab + (uint32_t)((wm * 32 + mt * 16 + (q & 1) * 8 + rlane) * 80
                                                + ks * 32 + (q >> 1) * 16);
                ldsm_x4(af[mt], addr);
            }
            uint32_t bf[NG][4];
#pragma unroll
            for (int p = 0; p < NG; p++) {
                // matrices: {n+0 B+0, n+0 B+16, n+8 B+0, n+8 B+16}
                uint32_t addr = Bb + (uint32_t)((wn * NT * 8 + p * 16 + (q >> 1) * 8 + rlane) * 80
                                                + ks * 32 + (q & 1) * 16);
                ldsm_x4(bf[p], addr);
            }
#pragma unroll
            for (int p = 0; p < NG; p++)
#pragma unroll
                for (int hh = 0; hh < 2; hh++)
#pragma unroll
                    for (int mt = 0; mt < 2; mt++)
                        mma16(acc[mt][2 * p + hh], af[mt], bf[p][2 * hh], bf[p][2 * hh + 1]);
        }
    };

    ldchunk(kc0, 0);
    ldchunk(kc0 + 1, 1);
    ldchunk(kc0 + 2, 2);
#pragma unroll 1
    for (int i = 0; i < 125; i++) {
        WAITG(2);
        __syncthreads();
        if (i + 3 < 125) ldchunk(kc0 + i + 3, (i + 3) & 3);
        else             CP_COMMIT();            // keep group count uniform for WAITG
        compute(i & 3);
    }

    // epilogue: c0,c1 -> (row g, cols 2tig,2tig+1); c2,c3 -> row g+8
#pragma unroll
    for (int mt = 0; mt < 2; mt++)
#pragma unroll
        for (int nt = 0; nt < NT; nt++) {
            int gcol = wn * NT * 8 + nt * 8 + tig * 2;
            int g = gcol >> 6, cc = gcol & 63;
            float* O = g_part[pbase + g * pstride];
            int r = row0 + wm * 32 + mt * 16 + gid;
            if (r < Nn)
                *(float2*)&O[(size_t)r * 64 + cc] =
                    make_float2(acc[mt][nt][0], acc[mt][nt][1]);
            if (r + 8 < Nn)
                *(float2*)&O[(size_t)(r + 8) * 64 + cc] =
                    make_float2(acc[mt][nt][2], acc[mt][nt][3]);
        }
}

// grid = 282: blocks [0,188) h-pass (94 M-tiles x 2 K-halves), [188,282) x-pass.
__global__ void __launch_bounds__(256, 2) k_gemm_mma() {
    extern __shared__ char smem[];
    uint32_t sb = smem_u32(smem);
    int bx = blockIdx.x;
    if (bx < 188) {
        int mt = bx >> 1, half = bx & 1;
        gemm_body<2>(g_Th, g_Bth, KH, half * 125, mt * 64, 3 + half, 2, sb);
    } else {
        gemm_body<3>(g_Tx, g_Btx, KX, 0, (bx - 188) * 64, 0, 1, sb);
    }
}

// ---------------- kernel 7: root GEMVs (fp32) + bias + GRU gates ----------------
__global__ void k_gates(const float* __restrict__ x, const float* __restrict__ hidden,
                        const float* __restrict__ Rxr, const float* __restrict__ Bxr,
                        const float* __restrict__ Rxz, const float* __restrict__ Bxz,
                        const float* __restrict__ Rxn, const float* __restrict__ Bxn,
                        const float* __restrict__ Rhr, const float* __restrict__ Bhr,
                        const float* __restrict__ Rhz, const float* __restrict__ Bhz,
                        float* __restrict__ out) {
    __shared__ float xs[4][32];
    __shared__ float hs[4][64];
    int tid = threadIdx.x;
    int nb = blockIdx.x * 4;
    if (tid < 128) {
        int nl = tid >> 5, i = tid & 31, n = nb + nl;
        xs[nl][i] = (n < Nn) ? x[n * 32 + i] : 0.f;
    }
    {
        int nl = tid >> 6, c = tid & 63, n = nb + nl;
        hs[nl][c] = (n < Nn) ? hidden[n * 64 + c] : 0.f;
    }
    __syncthreads();
    int nl = tid >> 6, c = tid & 63, n = nb + nl;
    if (n >= Nn) return;
    size_t i = (size_t)n * 64 + c;
    float xr = g_part[0][i] + Bxr[c];
    float xz = g_part[1][i] + Bxz[c];
    float xn = g_part[2][i] + Bxn[c];
    float hr = g_part[3][i] + g_part[4][i] + Bhr[c];
    float hz = g_part[5][i] + g_part[6][i] + Bhz[c];
#pragma unroll 8
    for (int k = 0; k < 32; k++) {
        float xv = xs[nl][k];
        xr += xv * Rxr[k * 64 + c];
        xz += xv * Rxz[k * 64 + c];
        xn += xv * Rxn[k * 64 + c];
    }
#pragma unroll 8
    for (int k = 0; k < 64; k++) {
        float hv = hs[nl][k];
        hr += hv * Rhr[k * 64 + c];
        hz += hv * Rhz[k * 64 + c];
    }
    float r = 1.0f / (1.0f + expf(-(xr + hr)));
    float z = 1.0f / (1.0f + expf(-(xz + hz)));
    float nno = tanhf(xn + r * hr);                 // faithful hr reuse
    out[i] = (1.0f - z) * nno + z * hs[nl][c];
}

// ---------------- launch ----------------
extern "C" void kernel_launch(void* const* d_in, const int* in_sizes, int n_in,
                              void* d_out, int out_size) {
    const float* x      = (const float*)d_in[0];
    const float* hidden = (const float*)d_in[1];
    const int*   ei     = (const int*)d_in[2];
    const float* attr   = (const float*)d_in[3];
    const float* Wxr = (const float*)d_in[4];
    const float* Rxr = (const float*)d_in[5];
    const float* Bxr = (const float*)d_in[6];
    const float* Whr = (const float*)d_in[7];
    const float* Rhr = (const float*)d_in[8];
    const float* Bhr = (const float*)d_in[9];
    const float* Wxz = (const float*)d_in[10];
    const float* Rxz = (const float*)d_in[11];
    const float* Bxz = (const float*)d_in[12];
    const float* Whz = (const float*)d_in[13];
    const float* Rhz = (const float*)d_in[14];
    const float* Bhz = (const float*)d_in[15];
    const float* Wxn = (const float*)d_in[16];
    const float* Rxn = (const float*)d_in[17];
    const float* Bxn = (const float*)d_in[18];
    // d_in[19..21] (W_hn/root_hn/b_hn) are dead in the reference.
    float* out = (float*)d_out;
    (void)in_sizes; (void)n_in; (void)out_size;

    cudaFuncSetAttribute(k_gemm_mma, cudaFuncAttributeMaxDynamicSharedMemorySize,
                         NSTG * STAGE);

    k_count<<<(Ee + 255) / 256, 256>>>(ei);                   // #1 (g_deg pre-zeroed)
    k_scan<<<1, 1024>>>();                                    // #2 (clears g_deg)
    k_edge<<<(Ee + 255) / 256, 256>>>(attr, ei);              // #3 (g_fill pre-zeroed)
    k_scatter<<<Nn, 192>>>(x, hidden);                        // #4 -> ncu window, clears g_fill
    k_transpose<<<dim3(250, 5), 256>>>(Wxr, Wxz, Wxn, Whr, Whz);
    k_gemm_mma<<<282, 256, NSTG * STAGE>>>();
    k_gates<<<(Nn + 3) / 4, 256>>>(x, hidden, Rxr, Bxr, Rxz, Bxz, Rxn, Bxn,
                                   Rhr, Bhr, Rhz, Bhz, out);
}

// round 17
// speedup vs baseline: 1.6874x; 1.0959x over previous
#include <cuda_runtime.h>
#include <cuda_bf16.h>
#include <math.h>
#include <stdint.h>

#define Nn   6000
#define Ee   192000
#define CINc 32
#define CHID 64
#define Kk   125
#define KX   4000        // Kk*CINc
#define KH   8000        // Kk*CHID

// ---------------- device scratch ----------------
__device__ __nv_bfloat16 g_Tx[(size_t)Nn * KX];   // bf16, pre-scaled by 1/deg
__device__ __nv_bfloat16 g_Th[(size_t)Nn * KH];
__device__ __nv_bfloat16 g_Btx[192 * KX];         // [co,k]: {Wxr,Wxz,Wxn} transposed
__device__ __nv_bfloat16 g_Bth[128 * KH];         // [co,k]: {Whr,Whz} transposed
__device__ float g_part[7][Nn * CHID];            // 0=XR 1=XZ 2=XN 3,4=HR halves 5,6=HZ halves
__device__ int   g_deg[Nn];                       // zeroed by k_scan (for next call)
__device__ int   g_fill[Nn];                      // zeroed by k_scatter (for next call)
__device__ int   g_rowstart[Nn + 1];
__device__ int   g_srcs[Ee];                      // CSR-ordered source node ids
__device__ uint32_t g_pidx[2][Ee];                // per-parity-half packed corner indices (4 x u8)
__device__ float4   g_pval[2][Ee];                // per-parity-half basis weights

// ---------------- PTX helpers (compute_103-safe: sm_80+ features only) ----------------
__device__ __forceinline__ uint32_t smem_u32(const void* p) {
    uint32_t a;
    asm("{ .reg .u64 t; cvta.to.shared.u64 t, %1; cvt.u32.u64 %0, t; }" : "=r"(a) : "l"(p));
    return a;
}
__device__ __forceinline__ void cpasync16(uint32_t dst, const void* src, int src_bytes) {
    asm volatile("cp.async.cg.shared.global [%0], [%1], 16, %2;"
                 :: "r"(dst), "l"(src), "r"(src_bytes) : "memory");
}
#define CP_COMMIT() asm volatile("cp.async.commit_group;" ::: "memory")
#define WAITG(n)    asm volatile("cp.async.wait_group " #n ";" ::: "memory")

__device__ __forceinline__ void ldsm_x4(uint32_t* r, uint32_t addr) {
    asm volatile("ldmatrix.sync.aligned.m8n8.x4.shared.b16 {%0,%1,%2,%3}, [%4];"
                 : "=r"(r[0]), "=r"(r[1]), "=r"(r[2]), "=r"(r[3]) : "r"(addr));
}
__device__ __forceinline__ void mma16(float* d, const uint32_t* a, uint32_t b0, uint32_t b1) {
    asm volatile(
        "mma.sync.aligned.m16n8k16.row.col.f32.bf16.bf16.f32 "
        "{%0,%1,%2,%3}, {%4,%5,%6,%7}, {%8,%9}, {%0,%1,%2,%3};"
        : "+f"(d[0]), "+f"(d[1]), "+f"(d[2]), "+f"(d[3])
        : "r"(a[0]), "r"(a[1]), "r"(a[2]), "r"(a[3]), "r"(b0), "r"(b1));
}

// ---------------- kernel 1: degree histogram ----------------
__global__ void k_count(const int* __restrict__ ei) {
    int e = blockIdx.x * blockDim.x + threadIdx.x;
    if (e < Ee) atomicAdd(&g_deg[ei[Ee + e]], 1);
}

// ---------------- kernel 2: exclusive scan (single block) + clear g_deg ----------------
__global__ void k_scan() {
    __shared__ int sh[1024];
    int tid = threadIdx.x;
    const int CH = 6;
    int base = tid * CH;
    int local[CH];
    int sum = 0;
#pragma unroll
    for (int q = 0; q < CH; q++) {
        int i = base + q;
        int v = 0;
        if (i < Nn) { v = g_deg[i]; g_deg[i] = 0; }   // read + clear for next call
        local[q] = sum;
        sum += v;
    }
    sh[tid] = sum;
    __syncthreads();
    for (int off = 1; off < 1024; off <<= 1) {
        int v = 0;
        if (tid >= off) v = sh[tid - off];
        __syncthreads();
        sh[tid] += v;
        __syncthreads();
    }
    int excl = (tid > 0) ? sh[tid - 1] : 0;
#pragma unroll
    for (int q = 0; q < CH; q++) {
        int i = base + q;
        if (i < Nn) g_rowstart[i] = excl + local[q];
    }
    if (tid == 1023) g_rowstart[Nn] = sh[1023];
}

// ---------------- kernel 3: per-edge basis, CSR order, parity-presorted ----------------
// Corner s has idx parity = base_parity ^ popcount(s). Group A = {0,3,5,6} (even
// popcount -> parity == bp), group B = {1,2,4,7}. Half bp gets A, half 1-bp gets B.
__global__ void k_edge(const float* __restrict__ attr, const int* __restrict__ ei) {
    int e = blockIdx.x * blockDim.x + threadIdx.x;
    if (e >= Ee) return;
    float fr[3]; int i0[3];
#pragma unroll
    for (int d = 0; d < 3; d++) {
        float u = attr[e * 3 + d] * 4.0f;
        int i = (int)floorf(u);
        i = i < 0 ? 0 : (i > 3 ? 3 : i);
        fr[d] = u - (float)i;
        i0[d] = i;
    }
    int dst = ei[Ee + e];
    int p = atomicAdd(&g_fill[dst], 1);
    int slot = g_rowstart[dst] + p;
    g_srcs[slot] = ei[e];

    uint32_t id[8]; float w[8];
#pragma unroll
    for (int s = 0; s < 8; s++) {
        int b0 = s & 1, b1 = (s >> 1) & 1, b2 = (s >> 2) & 1;
        id[s] = (uint32_t)((i0[0] + b0) * 25 + (i0[1] + b1) * 5 + (i0[2] + b2));
        w[s] = (b0 ? fr[0] : 1.0f - fr[0]) *
               (b1 ? fr[1] : 1.0f - fr[1]) *
               (b2 ? fr[2] : 1.0f - fr[2]);
    }
    uint32_t wA = id[0] | (id[3] << 8) | (id[5] << 16) | (id[6] << 24);
    uint32_t wB = id[1] | (id[2] << 8) | (id[4] << 16) | (id[7] << 24);
    float4 vA = make_float4(w[0], w[3], w[5], w[6]);
    float4 vB = make_float4(w[1], w[2], w[4], w[7]);
    int bp = (i0[0] + i0[1] + i0[2]) & 1;             // parity of group A
    g_pidx[bp][slot]     = wA;  g_pval[bp][slot]     = vA;
    g_pidx[bp ^ 1][slot] = wB;  g_pval[bp ^ 1][slot] = vB;
}

// ---------------- kernel 4: per-node scatter, parity halves, select-free ----------------
// 192 threads = 96 channels x 2 parity halves. Half h reads its pre-sorted stream:
// 4B packed idx + 16B weights per edge -> 4 unconditional RMWs. No selects.
__global__ __launch_bounds__(192) void k_scatter(const float* __restrict__ x,
                                                 const float* __restrict__ hidden) {
    __shared__ float Tsh[Kk * 96];
    int n = blockIdx.x;
    int t = threadIdx.x;
    int c = t % 96, h = t / 96;
    for (int i = t; i < Kk * 96; i += 192) Tsh[i] = 0.0f;
    int rs = g_rowstart[n], re = g_rowstart[n + 1];
    if (t == 0) g_fill[n] = 0;                    // clear for next call
    float inv = 1.0f / (float)max(re - rs, 1);
    __syncthreads();

    // hoist x-vs-hidden source select (uniform per thread)
    const float* fb;
    int fstride;
    if (c < CINc) { fb = x + c;                fstride = CINc; }
    else          { fb = hidden + (c - CINc);  fstride = CHID; }
    const uint32_t* __restrict__ pib = g_pidx[h];
    const float4*  __restrict__ pvb = g_pval[h];
    float* Tp = Tsh + c;

    int j = rs;
    int head = (re - rs) & 3;
    for (int q = 0; q < head; q++, j++) {        // <=3 singles to align main loop
        int s0 = __ldg(&g_srcs[j]);
        uint32_t pw = __ldg(&pib[j]);
        float4 v = __ldg(&pvb[j]);
        float xv = __ldg(&fb[(size_t)s0 * fstride]);
        Tp[(pw & 0xFF) * 96]         += v.x * xv;
        Tp[((pw >> 8) & 0xFF) * 96]  += v.y * xv;
        Tp[((pw >> 16) & 0xFF) * 96] += v.z * xv;
        Tp[(pw >> 24) * 96]          += v.w * xv;
    }
#pragma unroll 1
    for (; j < re; j += 4) {                     // branch-free 4x body: all loads batch
        int      srcv[4];
        uint32_t piv[4];
        float4   vv[4];
        float    xvv[4];
#pragma unroll
        for (int q = 0; q < 4; q++) {
            srcv[q] = __ldg(&g_srcs[j + q]);
            piv[q]  = __ldg(&pib[j + q]);
            vv[q]   = __ldg(&pvb[j + q]);
        }
#pragma unroll
        for (int q = 0; q < 4; q++)
            xvv[q] = __ldg(&fb[(size_t)srcv[q] * fstride]);
#pragma unroll
        for (int q = 0; q < 4; q++) {
            uint32_t pw = piv[q];
            float4 v = vv[q];
            float xv = xvv[q];
            Tp[(pw & 0xFF) * 96]         += v.x * xv;
            Tp[((pw >> 8) & 0xFF) * 96]  += v.y * xv;
            Tp[((pw >> 16) & 0xFF) * 96] += v.z * xv;
            Tp[(pw >> 24) * 96]          += v.w * xv;
        }
    }
    __syncthreads();

    // writeout: half 0 -> k [0,63), half 1 -> k [63,125)
    int k0 = h ? 63 : 0, k1 = h ? 125 : 63;
    if (c < CINc) {
        __nv_bfloat16* o = g_Tx + (size_t)n * KX + c;
        for (int k = k0; k < k1; k++) o[k * CINc] = __float2bfloat16(Tsh[k * 96 + c] * inv);
    } else {
        __nv_bfloat16* o = g_Th + (size_t)n * KH + (c - CINc);
        for (int k = k0; k < k1; k++) o[k * CHID] = __float2bfloat16(Tsh[k * 96 + c] * inv);
    }
}

// ---------------- kernel 5: transpose W -> Bt [N,K] K-major, bf16 ----------------
__global__ void k_transpose(const float* __restrict__ Wxr, const float* __restrict__ Wxz,
                            const float* __restrict__ Wxn, const float* __restrict__ Whr,
                            const float* __restrict__ Whz) {
    __shared__ float sh[32][65];
    int conv = blockIdx.y;
    const float* W; __nv_bfloat16* dst; int Kd;
    switch (conv) {
        case 0:  W = Wxr; dst = g_Btx;                     Kd = KX; break;
        case 1:  W = Wxz; dst = g_Btx + (size_t)64 * KX;   Kd = KX; break;
        case 2:  W = Wxn; dst = g_Btx + (size_t)128 * KX;  Kd = KX; break;
        case 3:  W = Whr; dst = g_Bth;                     Kd = KH; break;
        default: W = Whz; dst = g_Bth + (size_t)64 * KH;   Kd = KH; break;
    }
    int k0 = blockIdx.x * 32;
    if (k0 >= Kd) return;
    int tid = threadIdx.x;
#pragma unroll
    for (int w = 0; w < 8; w++) {
        int idx = w * 256 + tid, kk = idx >> 6, c = idx & 63;
        sh[kk][c] = W[(size_t)(k0 + kk) * 64 + c];
    }
    __syncthreads();
#pragma unroll
    for (int w = 0; w < 8; w++) {
        int idx = w * 256 + tid, c = idx >> 5, kk = idx & 31;
        dst[(size_t)c * Kd + k0 + kk] = __float2bfloat16(sh[kk][c]);
    }
}

// ---------------- kernel 6: bf16 mma.sync GEMM (ldmatrix fragments) ----------------
// BM=64, BK=32 (bf16), 256 threads = 8 warps (2M x 4N), 4-stage cp.async pipeline.
// Smem rows padded to 80B: 16B cp.async alignment; 8 LDSM rows at word offsets
// {0,20,8,28,16,4,24,12} mod 32 -> all banks covered, conflict-free.
#define STAGE 20480
#define NSTG  4

template<int NG>
__device__ __forceinline__ void gemm_body(const __nv_bfloat16* __restrict__ A,
                                          const __nv_bfloat16* __restrict__ Bt,
                                          int Kd, int kc0, int row0,
                                          int pbase, int pstride, uint32_t sb) {
    const int NT = NG * 2;                       // 8-wide N subtiles per warp
    int t = threadIdx.x;
    int w = t >> 5, lane = t & 31;
    int wm = w & 1, wn = w >> 1;
    int gid = lane >> 2, tig = lane & 3;
    int rlane = lane & 7, q = lane >> 3;         // ldmatrix lane decomposition

    float acc[2][NT][4];
#pragma unroll
    for (int mt = 0; mt < 2; mt++)
#pragma unroll
        for (int nt = 0; nt < NT; nt++)
#pragma unroll
            for (int p = 0; p < 4; p++) acc[mt][nt][p] = 0.0f;

    auto ldchunk = [&](int kc, int s) {
        uint32_t Ab = sb + s * STAGE;
        uint32_t Bb = Ab + 5120;
        int kb = kc * 32;
        {   // A: 64 rows x 64B = 256 x 16B, one per thread
            int row = t >> 2, c4 = t & 3;
            int m = row0 + row;
            int mc = m < Nn ? m : 0;
            cpasync16(Ab + (uint32_t)(row * 80 + c4 * 16),
                      A + (size_t)mc * Kd + kb + c4 * 8, m < Nn ? 16 : 0);
        }
#pragma unroll
        for (int p = 0; p < NG; p++) {           // B: NG*64 rows x 64B
            int idx = p * 256 + t, row = idx >> 2, c4 = idx & 3;
            cpasync16(Bb + (uint32_t)(row * 80 + c4 * 16),
                      Bt + (size_t)row * Kd + kb + c4 * 8, 16);
        }
        CP_COMMIT();
    };

    auto compute = [&](int s) {
        uint32_t Ab = sb + s * STAGE;
        uint32_t Bb = Ab + 5120;
#pragma unroll
        for (int ks = 0; ks < 2; ks++) {         // two k16 steps per 32-wide chunk
            uint32_t af[2][4];
#pragma unroll
            for (int mt = 0; mt < 2; mt++) {
                // matrices: {rows+0 B+0, rows+8 B+0, rows+0 B+16, rows+8 B+16}
                uint32_t addr = Ab + (uint32_t)((wm * 32 + mt * 16 + (q & 1) * 8 + rlane) * 80
                                                + ks * 32 + (q >> 1) * 16);
                ldsm_x4(af[mt], addr);
            }
            uint32_t bf[NG][4];
#pragma unroll
            for (int p = 0; p < NG; p++) {
                // matrices: {n+0 B+0, n+0 B+16, n+8 B+0, n+8 B+16}
                uint32_t addr = Bb + (uint32_t)((wn * NT * 8 + p * 16 + (q >> 1) * 8 + rlane) * 80
                                                + ks * 32 + (q & 1) * 16);
                ldsm_x4(bf[p], addr);
            }
#pragma unroll
            for (int p = 0; p < NG; p++)
#pragma unroll
                for (int hh = 0; hh < 2; hh++)
#pragma unroll
                    for (int mt = 0; mt < 2; mt++)
                        mma16(acc[mt][2 * p + hh], af[mt], bf[p][2 * hh], bf[p][2 * hh + 1]);
        }
    };

    ldchunk(kc0, 0);
    ldchunk(kc0 + 1, 1);
    ldchunk(kc0 + 2, 2);
#pragma unroll 1
    for (int i = 0; i < 125; i++) {
        WAITG(2);
        __syncthreads();
        if (i + 3 < 125) ldchunk(kc0 + i + 3, (i + 3) & 3);
        else             CP_COMMIT();            // keep group count uniform for WAITG
        compute(i & 3);
    }

    // epilogue: c0,c1 -> (row g, cols 2tig,2tig+1); c2,c3 -> row g+8
#pragma unroll
    for (int mt = 0; mt < 2; mt++)
#pragma unroll
        for (int nt = 0; nt < NT; nt++) {
            int gcol = wn * NT * 8 + nt * 8 + tig * 2;
            int g = gcol >> 6, cc = gcol & 63;
            float* O = g_part[pbase + g * pstride];
            int r = row0 + wm * 32 + mt * 16 + gid;
            if (r < Nn)
                *(float2*)&O[(size_t)r * 64 + cc] =
                    make_float2(acc[mt][nt][0], acc[mt][nt][1]);
            if (r + 8 < Nn)
                *(float2*)&O[(size_t)(r + 8) * 64 + cc] =
                    make_float2(acc[mt][nt][2], acc[mt][nt][3]);
        }
}

// grid = 282: blocks [0,188) h-pass (94 M-tiles x 2 K-halves), [188,282) x-pass.
__global__ void __launch_bounds__(256, 2) k_gemm_mma() {
    extern __shared__ char smem[];
    uint32_t sb = smem_u32(smem);
    int bx = blockIdx.x;
    if (bx < 188) {
        int mt = bx >> 1, half = bx & 1;
        gemm_body<2>(g_Th, g_Bth, KH, half * 125, mt * 64, 3 + half, 2, sb);
    } else {
        gemm_body<3>(g_Tx, g_Btx, KX, 0, (bx - 188) * 64, 0, 1, sb);
    }
}

// ---------------- kernel 7: root GEMVs (fp32) + bias + GRU gates ----------------
__global__ void k_gates(const float* __restrict__ x, const float* __restrict__ hidden,
                        const float* __restrict__ Rxr, const float* __restrict__ Bxr,
                        const float* __restrict__ Rxz, const float* __restrict__ Bxz,
                        const float* __restrict__ Rxn, const float* __restrict__ Bxn,
                        const float* __restrict__ Rhr, const float* __restrict__ Bhr,
                        const float* __restrict__ Rhz, const float* __restrict__ Bhz,
                        float* __restrict__ out) {
    __shared__ float xs[4][32];
    __shared__ float hs[4][64];
    int tid = threadIdx.x;
    int nb = blockIdx.x * 4;
    if (tid < 128) {
        int nl = tid >> 5, i = tid & 31, n = nb + nl;
        xs[nl][i] = (n < Nn) ? x[n * 32 + i] : 0.f;
    }
    {
        int nl = tid >> 6, c = tid & 63, n = nb + nl;
        hs[nl][c] = (n < Nn) ? hidden[n * 64 + c] : 0.f;
    }
    __syncthreads();
    int nl = tid >> 6, c = tid & 63, n = nb + nl;
    if (n >= Nn) return;
    size_t i = (size_t)n * 64 + c;
    float xr = g_part[0][i] + Bxr[c];
    float xz = g_part[1][i] + Bxz[c];
    float xn = g_part[2][i] + Bxn[c];
    float hr = g_part[3][i] + g_part[4][i] + Bhr[c];
    float hz = g_part[5][i] + g_part[6][i] + Bhz[c];
#pragma unroll 8
    for (int k = 0; k < 32; k++) {
        float xv = xs[nl][k];
        xr += xv * Rxr[k * 64 + c];
        xz += xv * Rxz[k * 64 + c];
        xn += xv * Rxn[k * 64 + c];
    }
#pragma unroll 8
    for (int k = 0; k < 64; k++) {
        float hv = hs[nl][k];
        hr += hv * Rhr[k * 64 + c];
        hz += hv * Rhz[k * 64 + c];
    }
    float r = 1.0f / (1.0f + expf(-(xr + hr)));
    float z = 1.0f / (1.0f + expf(-(xz + hz)));
    float nno = tanhf(xn + r * hr);                 // faithful hr reuse
    out[i] = (1.0f - z) * nno + z * hs[nl][c];
}

// ---------------- launch ----------------
extern "C" void kernel_launch(void* const* d_in, const int* in_sizes, int n_in,
                              void* d_out, int out_size) {
    const float* x      = (const float*)d_in[0];
    const float* hidden = (const float*)d_in[1];
    const int*   ei     = (const int*)d_in[2];
    const float* attr   = (const float*)d_in[3];
    const float* Wxr = (const float*)d_in[4];
    const float* Rxr = (const float*)d_in[5];
    const float* Bxr = (const float*)d_in[6];
    const float* Whr = (const float*)d_in[7];
    const float* Rhr = (const float*)d_in[8];
    const float* Bhr = (const float*)d_in[9];
    const float* Wxz = (const float*)d_in[10];
    const float* Rxz = (const float*)d_in[11];
    const float* Bxz = (const float*)d_in[12];
    const float* Whz = (const float*)d_in[13];
    const float* Rhz = (const float*)d_in[14];
    const float* Bhz = (const float*)d_in[15];
    const float* Wxn = (const float*)d_in[16];
    const float* Rxn = (const float*)d_in[17];
    const float* Bxn = (const float*)d_in[18];
    // d_in[19..21] (W_hn/root_hn/b_hn) are dead in the reference.
    float* out = (float*)d_out;
    (void)in_sizes; (void)n_in; (void)out_size;

    cudaFuncSetAttribute(k_gemm_mma, cudaFuncAttributeMaxDynamicSharedMemorySize,
                         NSTG * STAGE);

    k_count<<<(Ee + 255) / 256, 256>>>(ei);                   // #1 (g_deg pre-zeroed)
    k_scan<<<1, 1024>>>();                                    // #2 (clears g_deg)
    k_edge<<<(Ee + 255) / 256, 256>>>(attr, ei);              // #3 (g_fill pre-zeroed)
    k_scatter<<<Nn, 192>>>(x, hidden);                        // #4 -> ncu window, clears g_fill
    k_transpose<<<dim3(250, 5), 256>>>(Wxr, Wxz, Wxn, Whr, Whz);
    k_gemm_mma<<<282, 256, NSTG * STAGE>>>();
    k_gates<<<(Nn + 3) / 4, 256>>>(x, hidden, Rxr, Bxr, Rxz, Bxz, Rxn, Bxn,
                                   Rhr, Bhr, Rhz, Bhz, out);
}